// round 15
// baseline (speedup 1.0000x reference)
#include <cuda_runtime.h>
#include <cuda_bf16.h>
#include <cuda_fp16.h>
#include <cstdint>
#include <cmath>

// ---------------------------------------------------------------------------
// Problem constants (fixed shapes)
// ---------------------------------------------------------------------------
#define BB 2
#define TT 2048
#define NE 2048          // N_EMBED
#define NH 16            // N_HEAD
#define NKV 4            // N_KV_HEAD
#define HD 128           // HEAD_DIM
#define MROWS (BB*TT)    // 4096
#define KVDIM (NKV*HD)   // 512
#define NQK (NE + KVDIM)      // 2560 (bf16 hi/lo packed rows)
#define NQKV (NE + 2*KVDIM)   // 3072

// ---------------------------------------------------------------------------
// Scratch (static device globals; no allocations allowed)
// ---------------------------------------------------------------------------
__device__ __nv_bfloat16 g_qr[(size_t)BB * NH * TT * HD];   // rope(q) bf16 [B,H,T,D]
__device__ __nv_bfloat16 g_kr[(size_t)BB * NKV * TT * HD];  // rope(k) bf16 [B,KV,T,D]
__device__ __half        g_v16[(size_t)BB * NKV * TT * HD]; // v fp16 [B,KV,T,D]
__device__ __half        g_o16[(size_t)MROWS * NE];         // attn out fp16
__device__ float g_cos[TT * (HD/2)];
__device__ float g_sin[TT * (HD/2)];

// operands for tensor-core GEMMs
__device__ __nv_bfloat16 g_xh[(size_t)MROWS * NE];
__device__ __nv_bfloat16 g_xl[(size_t)MROWS * NE];
__device__ __half        g_x16[(size_t)MROWS * NE];         // x fp16 (for V proj)
// packed transposed weights [N][K] hi/lo: rows 0..2047 Wq^T, 2048..2559 Wk^T
__device__ __nv_bfloat16 g_wqkh[(size_t)NQK * NE];
__device__ __nv_bfloat16 g_wqkl[(size_t)NQK * NE];
__device__ __half        g_wv16[(size_t)KVDIM * NE];        // Wv^T fp16 [N][K]
__device__ __half        g_wo16[(size_t)NE * NE];           // Wo^T fp16 [N][K]

// ---------------------------------------------------------------------------
// Helpers (baseline PTX only — no sm_103a-suffixed features)
// ---------------------------------------------------------------------------
__device__ __forceinline__ uint32_t smem_u32(const void* p) {
    uint32_t a;
    asm("{ .reg .u64 t; cvta.to.shared.u64 t, %1; cvt.u32.u64 %0, t; }" : "=r"(a) : "l"(p));
    return a;
}
__device__ __forceinline__ uint32_t sw128(uint32_t off) {
    return off ^ ((off >> 3) & 0x70);
}
__device__ __forceinline__ void cp16(uint32_t dst, const void* src) {
    asm volatile("cp.async.cg.shared.global [%0], [%1], 16;" :: "r"(dst), "l"(src) : "memory");
}
__device__ __forceinline__ void ldsm4(uint32_t* r, uint32_t addr) {
    asm volatile("ldmatrix.sync.aligned.m8n8.x4.shared.b16 {%0,%1,%2,%3}, [%4];"
                 : "=r"(r[0]), "=r"(r[1]), "=r"(r[2]), "=r"(r[3]) : "r"(addr));
}
__device__ __forceinline__ void ldsm4t(uint32_t* r, uint32_t addr) {
    asm volatile("ldmatrix.sync.aligned.m8n8.x4.trans.shared.b16 {%0,%1,%2,%3}, [%4];"
                 : "=r"(r[0]), "=r"(r[1]), "=r"(r[2]), "=r"(r[3]) : "r"(addr));
}
__device__ __forceinline__ void mma16816(float* c, const uint32_t* a, const uint32_t* b) {
    asm volatile(
        "mma.sync.aligned.m16n8k16.row.col.f32.bf16.bf16.f32 "
        "{%0,%1,%2,%3}, {%4,%5,%6,%7}, {%8,%9}, {%0,%1,%2,%3};"
        : "+f"(c[0]), "+f"(c[1]), "+f"(c[2]), "+f"(c[3])
        : "r"(a[0]), "r"(a[1]), "r"(a[2]), "r"(a[3]), "r"(b[0]), "r"(b[1]));
}
__device__ __forceinline__ void mma16816h(float* c, const uint32_t* a, const uint32_t* b) {
    asm volatile(
        "mma.sync.aligned.m16n8k16.row.col.f32.f16.f16.f32 "
        "{%0,%1,%2,%3}, {%4,%5,%6,%7}, {%8,%9}, {%0,%1,%2,%3};"
        : "+f"(c[0]), "+f"(c[1]), "+f"(c[2]), "+f"(c[3])
        : "r"(a[0]), "r"(a[1]), "r"(a[2]), "r"(a[3]), "r"(b[0]), "r"(b[1]));
}
// pack two f32 -> bf16x2 (lo -> low half), round-to-nearest-even
__device__ __forceinline__ uint32_t cvtpack(float lo, float hi) {
    uint32_t r;
    asm("cvt.rn.bf16x2.f32 %0, %1, %2;" : "=r"(r) : "f"(hi), "f"(lo));
    return r;
}
// pack two f32 -> f16x2 (lo -> low half)
__device__ __forceinline__ uint32_t cvtpackh(float lo, float hi) {
    uint32_t r;
    asm("cvt.rn.f16x2.f32 %0, %1, %2;" : "=r"(r) : "f"(hi), "f"(lo));
    return r;
}
__device__ __forceinline__ float lo_f(uint32_t p) { return __uint_as_float(p << 16); }
__device__ __forceinline__ float hi_f(uint32_t p) { return __uint_as_float(p & 0xffff0000u); }

// ---------------------------------------------------------------------------
// Fused prep kernel:
// blocks [0,5120)      Wq/Wk transposes + bf16 hi/lo split
//        [5120,6144)   Wv transpose -> fp16
//        [6144,10240)  Wo transpose -> fp16
//        [10240,14336) x split (bf16 hi/lo + fp16)
//        [14336,14848) rope table
// ---------------------------------------------------------------------------
__global__ void __launch_bounds__(256)
prep_kernel(const float* __restrict__ Wq, const float* __restrict__ Wk,
            const float* __restrict__ Wv, const float* __restrict__ Wo,
            const float* __restrict__ x,
            __nv_bfloat16* __restrict__ wqkh, __nv_bfloat16* __restrict__ wqkl,
            __half* __restrict__ wv16, __half* __restrict__ wo16,
            __nv_bfloat16* __restrict__ xh, __nv_bfloat16* __restrict__ xl,
            __half* __restrict__ x16,
            float* __restrict__ ct, float* __restrict__ st)
{
    int bid = blockIdx.x;
    if (bid < 5120) {
        __shared__ float t[32][33];
        int id = bid;
        const float* W;
        __nv_bfloat16 *Th, *Tl;
        int N;
        if (id < 4096) { W = Wq; Th = wqkh;                   Tl = wqkl;                   N = NE;    }
        else           { W = Wk; Th = wqkh + (size_t)NE * NE; Tl = wqkl + (size_t)NE * NE; N = KVDIM; id -= 4096; }
        const int ntiles = N / 32;
        const int n0 = (id % ntiles) * 32;
        const int k0 = (id / ntiles) * 32;
        const int tx = threadIdx.x & 31, ty = threadIdx.x >> 5;
        #pragma unroll
        for (int i = 0; i < 4; i++)
            t[ty + i * 8][tx] = W[(size_t)(k0 + ty + i * 8) * N + n0 + tx];
        __syncthreads();
        #pragma unroll
        for (int i = 0; i < 4; i++) {
            int n = n0 + ty + i * 8, k = k0 + tx;
            float v = t[tx][ty + i * 8];
            __nv_bfloat16 h = __float2bfloat16(v);
            Th[(size_t)n * NE + k] = h;
            Tl[(size_t)n * NE + k] = __float2bfloat16(v - __bfloat162float(h));
        }
    } else if (bid < 6144) {
        // Wv transpose -> fp16
        __shared__ float t[32][33];
        int id = bid - 5120;
        const int n0 = (id & 15) * 32;      // 512/32 = 16 tiles per row
        const int k0 = (id >> 4) * 32;
        const int tx = threadIdx.x & 31, ty = threadIdx.x >> 5;
        #pragma unroll
        for (int i = 0; i < 4; i++)
            t[ty + i * 8][tx] = Wv[(size_t)(k0 + ty + i * 8) * KVDIM + n0 + tx];
        __syncthreads();
        #pragma unroll
        for (int i = 0; i < 4; i++) {
            int n = n0 + ty + i * 8, k = k0 + tx;
            wv16[(size_t)n * NE + k] = __float2half(t[tx][ty + i * 8]);
        }
    } else if (bid < 10240) {
        // Wo transpose -> fp16
        __shared__ float t[32][33];
        int id = bid - 6144;
        const int n0 = (id & 63) * 32;      // 2048/32 = 64 tiles per row
        const int k0 = (id >> 6) * 32;
        const int tx = threadIdx.x & 31, ty = threadIdx.x >> 5;
        #pragma unroll
        for (int i = 0; i < 4; i++)
            t[ty + i * 8][tx] = Wo[(size_t)(k0 + ty + i * 8) * NE + n0 + tx];
        __syncthreads();
        #pragma unroll
        for (int i = 0; i < 4; i++) {
            int n = n0 + ty + i * 8, k = k0 + tx;
            wo16[(size_t)n * NE + k] = __float2half(t[tx][ty + i * 8]);
        }
    } else if (bid < 14336) {
        int i = (bid - 10240) * 256 + threadIdx.x;
        size_t base = (size_t)i * 8;
        float4 v0 = *(const float4*)(x + base);
        float4 v1 = *(const float4*)(x + base + 4);
        float vv[8] = {v0.x, v0.y, v0.z, v0.w, v1.x, v1.y, v1.z, v1.w};
        uint4 uh, ul, u16;
        uint32_t* ph = (uint32_t*)&uh;
        uint32_t* pl = (uint32_t*)&ul;
        uint32_t* p6 = (uint32_t*)&u16;
        #pragma unroll
        for (int j = 0; j < 4; j++) {
            uint32_t h = cvtpack(vv[2*j], vv[2*j+1]);
            ph[j] = h;
            pl[j] = cvtpack(vv[2*j] - lo_f(h), vv[2*j+1] - hi_f(h));
            p6[j] = cvtpackh(vv[2*j], vv[2*j+1]);
        }
        *(uint4*)(xh + base)  = uh;
        *(uint4*)(xl + base)  = ul;
        *(uint4*)(x16 + base) = u16;
    } else {
        int idx = (bid - 14336) * 256 + threadIdx.x;
        int t = idx >> 6;
        int i = idx & 63;
        double fr = exp(-((double)(2 * i) / (double)NE) * log(10000.0));
        float ff = (float)fr;
        float ang = __fmul_rn((float)t, ff);
        float s, c;
        sincosf(ang, &s, &c);
        ct[idx] = c;
        st[idx] = s;
    }
}

// ---------------------------------------------------------------------------
// QKV GEMM core (QK regions): split-bf16 C = Ah@Bh^T + Ah@Bl^T + Al@Bh^T
// BM=256, BN=128, BK=64, 512 threads (4m x 4n warps, warp tile 64x32),
// 2-stage cp.async pipeline, ONE __syncthreads per stage. (R11-proven)
// ---------------------------------------------------------------------------
#define STG_BYTES 98304
#define GEMM_SMEM (2*STG_BYTES + 1024)

__device__ __forceinline__ void gemm_core(
    const __nv_bfloat16* __restrict__ Ah, const __nv_bfloat16* __restrict__ Al,
    const __nv_bfloat16* __restrict__ BTh, const __nv_bfloat16* __restrict__ BTl,
    int K, int m0, int n0, uint32_t sb, int tid, float c[4][4][4])
{
    const int lane = tid & 31;
    const int wm   = (tid >> 5) >> 2;
    const int wn   = (tid >> 5) & 3;
    const int nstage = K / 64;

    #pragma unroll
    for (int im = 0; im < 4; im++)
        #pragma unroll
        for (int in = 0; in < 4; in++)
            #pragma unroll
            for (int j = 0; j < 4; j++) c[im][in][j] = 0.f;

    auto load_stage = [&](int s) {
        const int k0 = s * 64;
        const uint32_t stg = sb + (uint32_t)(s & 1) * STG_BYTES;
        #pragma unroll
        for (int i = 0; i < 12; i++) {
            int idx = tid + (i << 9);
            if (idx < 4096) {
                int mat = idx >> 11;
                int row = (idx >> 3) & 255;
                int q   = idx & 7;
                const __nv_bfloat16* src =
                    (mat ? Al : Ah) + (size_t)(m0 + row) * K + k0 + q * 8;
                cp16(stg + mat * 32768 + sw128((uint32_t)(row * 128 + q * 16)), src);
            } else {
                int rel = idx - 4096;
                int mat = rel >> 10;
                int row = (rel >> 3) & 127;
                int q   = rel & 7;
                const __nv_bfloat16* src =
                    (mat ? BTl : BTh) + (size_t)(n0 + row) * K + k0 + q * 8;
                cp16(stg + 65536 + mat * 16384 + sw128((uint32_t)(row * 128 + q * 16)), src);
            }
        }
    };

    load_stage(0);
    asm volatile("cp.async.commit_group;" ::: "memory");

    const int aRow  = (lane & 15);
    const int aKoff = (lane >> 4) << 4;
    const int bRow  = (lane & 7) + ((lane >> 4) << 3);
    const int bKoff = ((lane >> 3) & 1) << 4;

    for (int s = 0; s < nstage; s++) {
        asm volatile("cp.async.wait_group 0;" ::: "memory");
        __syncthreads();
        if (s + 1 < nstage) {
            load_stage(s + 1);
            asm volatile("cp.async.commit_group;" ::: "memory");
        }

        const uint32_t ab = sb + (uint32_t)(s & 1) * STG_BYTES;

        #pragma unroll
        for (int kk = 0; kk < 4; kk++) {
            const int kb = kk * 32;
            uint32_t b_h[8], b_l[8];
            #pragma unroll
            for (int ib = 0; ib < 2; ib++) {
                uint32_t off = sw128((uint32_t)((wn * 32 + ib * 16 + bRow) * 128 + kb + bKoff));
                ldsm4(&b_h[ib * 4], ab + 65536 + off);
                ldsm4(&b_l[ib * 4], ab + 81920 + off);
            }
            #pragma unroll
            for (int im = 0; im < 4; im++) {
                uint32_t a_h[4], a_l[4];
                uint32_t off = sw128((uint32_t)((wm * 64 + im * 16 + aRow) * 128 + kb + aKoff));
                ldsm4(a_h, ab + off);
                ldsm4(a_l, ab + 32768 + off);
                #pragma unroll
                for (int in = 0; in < 4; in++) {
                    const uint32_t* bh = &b_h[(in >> 1) * 4 + (in & 1) * 2];
                    const uint32_t* bl = &b_l[(in >> 1) * 4 + (in & 1) * 2];
                    mma16816(c[im][in], a_h, bh);
                    mma16816(c[im][in], a_l, bh);
                    mma16816(c[im][in], a_h, bl);
                }
            }
        }
    }
    __syncthreads();
}

// fp16 single-term core (V region / O-proj): C = A16 @ BT16^T
// Stage: A 32KB @0 | B 16KB @32K offset within stage region (reuse 65536 slot)
__device__ __forceinline__ void gemm_core_h(
    const __half* __restrict__ A, const __half* __restrict__ BT,
    int K, int m0, int n0, uint32_t sb, int tid, uint32_t stg_bytes, float c[4][4][4])
{
    const int lane = tid & 31;
    const int wm   = (tid >> 5) >> 2;
    const int wn   = (tid >> 5) & 3;
    const int nstage = K / 64;

    #pragma unroll
    for (int im = 0; im < 4; im++)
        #pragma unroll
        for (int in = 0; in < 4; in++)
            #pragma unroll
            for (int j = 0; j < 4; j++) c[im][in][j] = 0.f;

    auto load_stage = [&](int s) {
        const int k0 = s * 64;
        const uint32_t stg = sb + (uint32_t)(s & 1) * stg_bytes;
        #pragma unroll
        for (int i = 0; i < 6; i++) {
            int idx = tid + (i << 9);           // 0..3071
            if (idx < 2048) {
                int row = idx >> 3;
                int q   = idx & 7;
                cp16(stg + sw128((uint32_t)(row * 128 + q * 16)),
                     A + (size_t)(m0 + row) * K + k0 + q * 8);
            } else {
                int rel = idx - 2048;
                int row = rel >> 3;
                int q   = rel & 7;
                cp16(stg + 32768 + sw128((uint32_t)(row * 128 + q * 16)),
                     BT + (size_t)(n0 + row) * K + k0 + q * 8);
            }
        }
    };

    load_stage(0);
    asm volatile("cp.async.commit_group;" ::: "memory");

    const int aRow  = (lane & 15);
    const int aKoff = (lane >> 4) << 4;
    const int bRow  = (lane & 7) + ((lane >> 4) << 3);
    const int bKoff = ((lane >> 3) & 1) << 4;

    for (int s = 0; s < nstage; s++) {
        asm volatile("cp.async.wait_group 0;" ::: "memory");
        __syncthreads();
        if (s + 1 < nstage) {
            load_stage(s + 1);
            asm volatile("cp.async.commit_group;" ::: "memory");
        }

        const uint32_t ab = sb + (uint32_t)(s & 1) * stg_bytes;

        #pragma unroll
        for (int kk = 0; kk < 4; kk++) {
            const int kb = kk * 32;
            uint32_t b_f[8];
            #pragma unroll
            for (int ib = 0; ib < 2; ib++) {
                uint32_t off = sw128((uint32_t)((wn * 32 + ib * 16 + bRow) * 128 + kb + bKoff));
                ldsm4(&b_f[ib * 4], ab + 32768 + off);
            }
            #pragma unroll
            for (int im = 0; im < 4; im++) {
                uint32_t a_f[4];
                uint32_t off = sw128((uint32_t)((wm * 64 + im * 16 + aRow) * 128 + kb + aKoff));
                ldsm4(a_f, ab + off);
                #pragma unroll
                for (int in = 0; in < 4; in++)
                    mma16816h(c[im][in], a_f, &b_f[(in >> 1) * 4 + (in & 1) * 2]);
            }
        }
    }
    __syncthreads();
}

// ---------------------------------------------------------------------------
// QKV GEMM: Q/K split-bf16 3-term + RoPE epilogue; V fp16 single-term.
// 1D grid of 384: ids [0,64) = V tiles (launched first, cheap),
// ids [64,384) = QK tiles. BM=256, BN=128.
// ---------------------------------------------------------------------------
__global__ void __launch_bounds__(512, 1)
gemm_qkv_kernel(const __nv_bfloat16* __restrict__ Ah, const __nv_bfloat16* __restrict__ Al,
                const __nv_bfloat16* __restrict__ BTh, const __nv_bfloat16* __restrict__ BTl,
                const __half* __restrict__ x16, const __half* __restrict__ wv16,
                const float* __restrict__ bq, const float* __restrict__ bk,
                const float* __restrict__ bv,
                const float* __restrict__ ct, const float* __restrict__ st,
                __nv_bfloat16* __restrict__ qr, __nv_bfloat16* __restrict__ kr,
                __half* __restrict__ v16)
{
    extern __shared__ char dsm[];
    char* smbase = (char*)(((uintptr_t)dsm + 1023) & ~(uintptr_t)1023);
    const uint32_t sb = smem_u32(smbase);
    const int tid  = threadIdx.x;
    const int lane = tid & 31;
    const int wm   = (tid >> 5) >> 2;
    const int wn   = (tid >> 5) & 3;

    int lin = blockIdx.x;
    int colt, rowt, region;
    if (lin < 64) { colt = 20 + (lin & 3); rowt = lin >> 2; region = 2; }
    else {
        int r = lin - 64;
        colt = r % 20; rowt = r / 20;
        region = (colt >= 16) ? 1 : 0;
    }
    const int m0 = rowt * 256;
    const int n0 = colt * 128;

    float c[4][4][4];
    if (region == 2) {
        gemm_core_h(x16, wv16, NE, m0, n0 - NQK, sb, tid, STG_BYTES, c);
    } else {
        gemm_core(Ah, Al, BTh, BTl, NE, m0, n0, sb, tid, c);
    }

    #pragma unroll
    for (int im = 0; im < 4; im++) {
        const int r0 = m0 + wm * 64 + im * 16 + (lane >> 2);
        const int b  = r0 >> 11;
        const int t  = r0 & 2047;
        #pragma unroll
        for (int in = 0; in < 4; in++) {
            const int cc = n0 + wn * 32 + in * 8 + ((lane & 3) << 1);
            float b0, b1;
            if (region == 0)      { b0 = bq[cc];          b1 = bq[cc + 1]; }
            else if (region == 1) { b0 = bk[cc - NE];     b1 = bk[cc - NE + 1]; }
            else                  { b0 = bv[cc - NQK];    b1 = bv[cc - NQK + 1]; }
            float v0 = c[im][in][0] + b0, v1 = c[im][in][1] + b1;   // row t
            float v2 = c[im][in][2] + b0, v3 = c[im][in][3] + b1;   // row t+8
            const int dloc = cc & 127;
            if (region <= 1) {
                const int i  = dloc >> 1;
                float c0 = ct[t * 64 + i],       s0 = st[t * 64 + i];
                float c2 = ct[(t + 8) * 64 + i], s2 = st[(t + 8) * 64 + i];
                uint32_t p0 = cvtpack(v0 * c0 - v1 * s0, v0 * s0 + v1 * c0);
                uint32_t p2 = cvtpack(v2 * c2 - v3 * s2, v2 * s2 + v3 * c2);
                if (region == 0) {
                    const int h = cc >> 7;
                    size_t dst = ((size_t)((b * NH + h) * TT + t)) * HD + dloc;
                    *(uint32_t*)(qr + dst)          = p0;
                    *(uint32_t*)(qr + dst + 8 * HD) = p2;
                } else {
                    const int h = (cc - NE) >> 7;
                    size_t dst = ((size_t)((b * NKV + h) * TT + t)) * HD + dloc;
                    *(uint32_t*)(kr + dst)          = p0;
                    *(uint32_t*)(kr + dst + 8 * HD) = p2;
                }
            } else {
                const int h = (cc - NQK) >> 7;
                size_t dst = ((size_t)((b * NKV + h) * TT + t)) * HD + dloc;
                *(uint32_t*)(v16 + dst)          = cvtpackh(v0, v1);
                *(uint32_t*)(v16 + dst + 8 * HD) = cvtpackh(v2, v3);
            }
        }
    }
}

// ---------------------------------------------------------------------------
// Output projection GEMM: fp16 x fp16 single-term (+bias) -> fp32 out
// ---------------------------------------------------------------------------
#define OSTG_BYTES 49152
#define GEMMO_SMEM (2*OSTG_BYTES + 1024)

__global__ void __launch_bounds__(512, 1)
gemm_out_kernel(const __half* __restrict__ A, const __half* __restrict__ BT,
                const float* __restrict__ bias, float* __restrict__ C)
{
    extern __shared__ char dsm[];
    char* smbase = (char*)(((uintptr_t)dsm + 1023) & ~(uintptr_t)1023);
    const uint32_t sb = smem_u32(smbase);
    const int tid  = threadIdx.x;
    const int lane = tid & 31;
    const int wm   = (tid >> 5) >> 2;
    const int wn   = (tid >> 5) & 3;
    const int m0   = blockIdx.y * 256;
    const int n0   = blockIdx.x * 128;

    float c[4][4][4];
    gemm_core_h(A, BT, NE, m0, n0, sb, tid, OSTG_BYTES, c);

    #pragma unroll
    for (int im = 0; im < 4; im++) {
        const int r0 = m0 + wm * 64 + im * 16 + (lane >> 2);
        #pragma unroll
        for (int in = 0; in < 4; in++) {
            const int cc = n0 + wn * 32 + in * 8 + ((lane & 3) << 1);
            float2 bb = *(const float2*)&bias[cc];
            float2 o0, o1;
            o0.x = c[im][in][0] + bb.x;  o0.y = c[im][in][1] + bb.y;
            o1.x = c[im][in][2] + bb.x;  o1.y = c[im][in][3] + bb.y;
            *(float2*)&C[(size_t)r0 * NE + cc]       = o0;
            *(float2*)&C[(size_t)(r0 + 8) * NE + cc] = o1;
        }
    }
}

// ---------------------------------------------------------------------------
// Flash attention (causal, GQA). S=QK^T on bf16 mma (reference-exact);
// AV on fp16 P x fp16 V single term. BM=64, BN=64, 128 threads/4 warps,
// 3 CTAs/SM. Ring-2 {K,V} buffers, ONE sync per tile, prefetch AFTER sync.
// Q borrows buf1's K slot for tile 0. Epilogue writes fp16 o16.
// ---------------------------------------------------------------------------
#define AT_RS 272
#define AT_T64 (64 * AT_RS)
#define ATT_SMEM (4 * AT_T64 + 1024)

__global__ void __launch_bounds__(128, 3)
attn_mma_kernel(const __nv_bfloat16* __restrict__ qr, const __nv_bfloat16* __restrict__ kr,
                const __half* __restrict__ v16, __half* __restrict__ o16)
{
    extern __shared__ char dsm2[];
    char* smb = (char*)(((uintptr_t)dsm2 + 1023) & ~(uintptr_t)1023);
    const uint32_t sb = smem_u32(smb);

    const int tid  = threadIdx.x;
    const int lane = tid & 31;
    const int w    = tid >> 5;                              // 0..3
    const int mtb  = (int)gridDim.x - 1 - (int)blockIdx.x;  // heavy blocks first
    const int h    = blockIdx.y, b = blockIdx.z;
    const int m0   = mtb * 64;
    const int kv   = h >> 2;
    const int ntile = mtb + 1;

    const __nv_bfloat16* qg = qr  + ((size_t)(b * NH + h) * TT + m0) * HD;
    const __nv_bfloat16* kg = kr  + ((size_t)(b * NKV + kv) * TT) * HD;
    const __half*        vg = v16 + ((size_t)(b * NKV + kv) * TT) * HD;

    auto toff = [&](int buf, int which) -> uint32_t {
        return sb + (uint32_t)AT_T64 * (buf * 2 + which);
    };
    const uint32_t Q0 = toff(1, 0);
    auto load64 = [&](uint32_t dst, const void* srcbase, int tile) {
        const char* src = (const char*)srcbase + (size_t)tile * 64 * HD * 2;
        #pragma unroll
        for (int i = 0; i < 8; i++) {
            int idx = tid + i * 128;
            int row = idx >> 4, cq = idx & 15;
            cp16(dst + (uint32_t)(row * AT_RS + cq * 16), src + (size_t)row * HD * 2 + cq * 16);
        }
    };

    load64(Q0, qg, 0);
    load64(toff(0, 0), kg, 0);
    load64(toff(0, 1), vg, 0);
    asm volatile("cp.async.commit_group;" ::: "memory");

    uint32_t qf[8][4];
    float ov[16][4];
    #pragma unroll
    for (int n = 0; n < 16; n++) { ov[n][0] = ov[n][1] = ov[n][2] = ov[n][3] = 0.f; }
    float m_lo = -1e30f, m_hi = -1e30f, l_lo = 0.f, l_hi = 0.f;

    const int aRow = lane & 15;
    const int aK   = (lane >> 4) << 4;
    const int bRow = (lane & 7) + ((lane >> 4) << 3);
    const int bK   = ((lane >> 3) & 1) << 4;
    const int vRow = (lane & 7) + (((lane >> 3) & 1) << 3);
    const int vC   = (lane >> 4) << 4;

    for (int jt = 0; jt < ntile; jt++) {
        asm volatile("cp.async.wait_group 0;" ::: "memory");
        __syncthreads();
        if (jt == 0) {
            #pragma unroll
            for (int kt = 0; kt < 8; kt++)
                ldsm4(qf[kt], Q0 + (uint32_t)((w * 16 + aRow) * AT_RS + kt * 32 + aK));
            __syncthreads();
        }
        if (jt + 1 < ntile) {
            int nb = (jt + 1) & 1;
            load64(toff(nb, 0), kg, jt + 1);
            load64(toff(nb, 1), vg, jt + 1);
            asm volatile("cp.async.commit_group;" ::: "memory");
        }

        const int cbuf = jt & 1;
        const uint32_t kb = toff(cbuf, 0);
        const uint32_t vb = toff(cbuf, 1);

        // ---- S = Q @ K^T (bf16, reference-exact inputs) ----
        float sc[8][4];
        #pragma unroll
        for (int j = 0; j < 8; j++) { sc[j][0] = sc[j][1] = sc[j][2] = sc[j][3] = 0.f; }

        #pragma unroll
        for (int kt = 0; kt < 8; kt++) {
            #pragma unroll
            for (int ib = 0; ib < 4; ib++) {
                uint32_t bf[4];
                ldsm4(bf, kb + (uint32_t)((ib * 16 + bRow) * AT_RS + kt * 32 + bK));
                mma16816(sc[2 * ib],     qf[kt], bf);
                mma16816(sc[2 * ib + 1], qf[kt], bf + 2);
            }
        }

        // ---- causal mask (diagonal tile only) ----
        if (jt == ntile - 1) {
            const int rl = w * 16 + (lane >> 2);
            #pragma unroll
            for (int j = 0; j < 8; j++) {
                int gn = j * 8 + ((lane & 3) << 1);
                if (gn     > rl)     sc[j][0] = -1e30f;
                if (gn + 1 > rl)     sc[j][1] = -1e30f;
                if (gn     > rl + 8) sc[j][2] = -1e30f;
                if (gn + 1 > rl + 8) sc[j][3] = -1e30f;
            }
        }

        // ---- online softmax ----
        float vlo = -1e30f, vhi = -1e30f;
        #pragma unroll
        for (int j = 0; j < 8; j++) {
            vlo = fmaxf(vlo, fmaxf(sc[j][0], sc[j][1]));
            vhi = fmaxf(vhi, fmaxf(sc[j][2], sc[j][3]));
        }
        vlo = fmaxf(vlo, __shfl_xor_sync(0xffffffffu, vlo, 1));
        vlo = fmaxf(vlo, __shfl_xor_sync(0xffffffffu, vlo, 2));
        vhi = fmaxf(vhi, __shfl_xor_sync(0xffffffffu, vhi, 1));
        vhi = fmaxf(vhi, __shfl_xor_sync(0xffffffffu, vhi, 2));
        float mn_lo = fmaxf(m_lo, vlo), mn_hi = fmaxf(m_hi, vhi);
        float al_lo = __expf(m_lo - mn_lo), al_hi = __expf(m_hi - mn_hi);
        m_lo = mn_lo; m_hi = mn_hi;
        l_lo *= al_lo; l_hi *= al_hi;
        #pragma unroll
        for (int n = 0; n < 16; n++) {
            ov[n][0] *= al_lo; ov[n][1] *= al_lo;
            ov[n][2] *= al_hi; ov[n][3] *= al_hi;
        }

        uint32_t ph[8][2];
        #pragma unroll
        for (int j = 0; j < 8; j++) {
            float p0 = __expf(sc[j][0] - m_lo), p1 = __expf(sc[j][1] - m_lo);
            float p2 = __expf(sc[j][2] - m_hi), p3 = __expf(sc[j][3] - m_hi);
            l_lo += p0 + p1;  l_hi += p2 + p3;
            ph[j][0] = cvtpackh(p0, p1);
            ph[j][1] = cvtpackh(p2, p3);
        }

        // ---- O += P @ V  (fp16 x fp16, single term) ----
        #pragma unroll
        for (int kt = 0; kt < 4; kt++) {
            uint32_t ah[4] = { ph[2*kt][0], ph[2*kt][1], ph[2*kt+1][0], ph[2*kt+1][1] };
            #pragma unroll
            for (int np = 0; np < 4; np++) {
                uint32_t base = (uint32_t)((kt * 16 + vRow) * AT_RS + np * 64 + vC);
                uint32_t bh0[4], bh1[4];
                ldsm4t(bh0, vb + base);
                ldsm4t(bh1, vb + base + 32);
                mma16816h(ov[np*4+0], ah, bh0);
                mma16816h(ov[np*4+1], ah, bh0 + 2);
                mma16816h(ov[np*4+2], ah, bh1);
                mma16816h(ov[np*4+3], ah, bh1 + 2);
            }
        }
    }

    // ---- epilogue: normalize, write fp16 o16 ----
    l_lo += __shfl_xor_sync(0xffffffffu, l_lo, 1);
    l_lo += __shfl_xor_sync(0xffffffffu, l_lo, 2);
    l_hi += __shfl_xor_sync(0xffffffffu, l_hi, 1);
    l_hi += __shfl_xor_sync(0xffffffffu, l_hi, 2);
    const float inv_lo = 0.022097086912079608f / l_lo;
    const float inv_hi = 0.022097086912079608f / l_hi;
    const int rlo = m0 + w * 16 + (lane >> 2);
    size_t base = ((size_t)(b * TT) + rlo) * NE + h * HD;
    #pragma unroll
    for (int n = 0; n < 16; n++) {
        int d = n * 8 + ((lane & 3) << 1);
        *(uint32_t*)(o16 + base + d)          = cvtpackh(ov[n][0] * inv_lo, ov[n][1] * inv_lo);
        *(uint32_t*)(o16 + base + 8 * NE + d) = cvtpackh(ov[n][2] * inv_hi, ov[n][3] * inv_hi);
    }
}

// ---------------------------------------------------------------------------
// launch
// ---------------------------------------------------------------------------
extern "C" void kernel_launch(void* const* d_in, const int* in_sizes, int n_in,
                              void* d_out, int out_size)
{
    const float* x  = (const float*)d_in[0];
    const float* Wq = (const float*)d_in[1];
    const float* bq = (const float*)d_in[2];
    const float* Wk = (const float*)d_in[3];
    const float* bk = (const float*)d_in[4];
    const float* Wv = (const float*)d_in[5];
    const float* bv = (const float*)d_in[6];
    const float* Wo = (const float*)d_in[7];
    const float* bo = (const float*)d_in[8];
    float* out = (float*)d_out;

    float *ct, *st;
    __nv_bfloat16 *qr, *kr;
    __half *v16, *o16, *x16, *wv16, *wo16;
    __nv_bfloat16 *xh, *xl;
    __nv_bfloat16 *wqkh, *wqkl;
    cudaGetSymbolAddress((void**)&ct, g_cos);
    cudaGetSymbolAddress((void**)&st, g_sin);
    cudaGetSymbolAddress((void**)&qr, g_qr);
    cudaGetSymbolAddress((void**)&kr, g_kr);
    cudaGetSymbolAddress((void**)&v16, g_v16);
    cudaGetSymbolAddress((void**)&o16, g_o16);
    cudaGetSymbolAddress((void**)&x16, g_x16);
    cudaGetSymbolAddress((void**)&xh, g_xh);
    cudaGetSymbolAddress((void**)&xl, g_xl);
    cudaGetSymbolAddress((void**)&wqkh, g_wqkh);
    cudaGetSymbolAddress((void**)&wqkl, g_wqkl);
    cudaGetSymbolAddress((void**)&wv16, g_wv16);
    cudaGetSymbolAddress((void**)&wo16, g_wo16);

    cudaFuncSetAttribute(gemm_qkv_kernel, cudaFuncAttributeMaxDynamicSharedMemorySize, GEMM_SMEM);
    cudaFuncSetAttribute(gemm_out_kernel, cudaFuncAttributeMaxDynamicSharedMemorySize, GEMMO_SMEM);
    cudaFuncSetAttribute(attn_mma_kernel, cudaFuncAttributeMaxDynamicSharedMemorySize, ATT_SMEM);

    // fused prep (1 launch)
    prep_kernel<<<14848, 256>>>(Wq, Wk, Wv, Wo, x, wqkh, wqkl, wv16, wo16,
                                xh, xl, x16, ct, st);

    // fused QKV projection: V tiles (fp16, cheap) first, then QK tiles
    gemm_qkv_kernel<<<384, 512, GEMM_SMEM>>>(
        xh, xl, wqkh, wqkl, x16, wv16, bq, bk, bv, ct, st, qr, kr, v16);

    // attention (writes fp16 o16); 3 CTAs/SM
    {
        dim3 grid(TT / 64, NH, BB);
        attn_mma_kernel<<<grid, 128, ATT_SMEM>>>(qr, kr, v16, o16);
    }

    // output projection: fp16 single-term
    gemm_out_kernel<<<dim3(NE / 128, MROWS / 256), 512, GEMMO_SMEM>>>(
        o16, wo16, bo, out);
}

// round 16
// speedup vs baseline: 1.0102x; 1.0102x over previous
#include <cuda_runtime.h>
#include <cuda_bf16.h>
#include <cuda_fp16.h>
#include <cstdint>
#include <cmath>

// ---------------------------------------------------------------------------
// Problem constants (fixed shapes)
// ---------------------------------------------------------------------------
#define BB 2
#define TT 2048
#define NE 2048          // N_EMBED
#define NH 16            // N_HEAD
#define NKV 4            // N_KV_HEAD
#define HD 128           // HEAD_DIM
#define MROWS (BB*TT)    // 4096
#define KVDIM (NKV*HD)   // 512
#define NQK (NE + KVDIM)      // 2560 (bf16 hi/lo packed rows)
#define NQKV (NE + 2*KVDIM)   // 3072
#define NSM 148

// ---------------------------------------------------------------------------
// Scratch (static device globals; no allocations allowed)
// ---------------------------------------------------------------------------
__device__ __nv_bfloat16 g_qr[(size_t)BB * NH * TT * HD];   // rope(q) bf16 [B,H,T,D]
__device__ __nv_bfloat16 g_kr[(size_t)BB * NKV * TT * HD];  // rope(k) bf16 [B,KV,T,D]
__device__ __half        g_v16[(size_t)BB * NKV * TT * HD]; // v fp16 [B,KV,T,D]
__device__ __half        g_o16[(size_t)MROWS * NE];         // attn out fp16
__device__ float g_cos[TT * (HD/2)];
__device__ float g_sin[TT * (HD/2)];
__device__ uint32_t g_ctr[2];                               // work-steal counters

// operands for tensor-core GEMMs
__device__ __nv_bfloat16 g_xh[(size_t)MROWS * NE];
__device__ __nv_bfloat16 g_xl[(size_t)MROWS * NE];
__device__ __half        g_x16[(size_t)MROWS * NE];         // x fp16 (for V proj)
// packed transposed weights [N][K] hi/lo: rows 0..2047 Wq^T, 2048..2559 Wk^T
__device__ __nv_bfloat16 g_wqkh[(size_t)NQK * NE];
__device__ __nv_bfloat16 g_wqkl[(size_t)NQK * NE];
__device__ __half        g_wv16[(size_t)KVDIM * NE];        // Wv^T fp16 [N][K]
__device__ __half        g_wo16[(size_t)NE * NE];           // Wo^T fp16 [N][K]

// ---------------------------------------------------------------------------
// Helpers (baseline PTX only — no sm_103a-suffixed features)
// ---------------------------------------------------------------------------
__device__ __forceinline__ uint32_t smem_u32(const void* p) {
    uint32_t a;
    asm("{ .reg .u64 t; cvta.to.shared.u64 t, %1; cvt.u32.u64 %0, t; }" : "=r"(a) : "l"(p));
    return a;
}
__device__ __forceinline__ uint32_t sw128(uint32_t off) {
    return off ^ ((off >> 3) & 0x70);
}
__device__ __forceinline__ void cp16(uint32_t dst, const void* src) {
    asm volatile("cp.async.cg.shared.global [%0], [%1], 16;" :: "r"(dst), "l"(src) : "memory");
}
__device__ __forceinline__ void ldsm4(uint32_t* r, uint32_t addr) {
    asm volatile("ldmatrix.sync.aligned.m8n8.x4.shared.b16 {%0,%1,%2,%3}, [%4];"
                 : "=r"(r[0]), "=r"(r[1]), "=r"(r[2]), "=r"(r[3]) : "r"(addr));
}
__device__ __forceinline__ void ldsm4t(uint32_t* r, uint32_t addr) {
    asm volatile("ldmatrix.sync.aligned.m8n8.x4.trans.shared.b16 {%0,%1,%2,%3}, [%4];"
                 : "=r"(r[0]), "=r"(r[1]), "=r"(r[2]), "=r"(r[3]) : "r"(addr));
}
__device__ __forceinline__ void mma16816(float* c, const uint32_t* a, const uint32_t* b) {
    asm volatile(
        "mma.sync.aligned.m16n8k16.row.col.f32.bf16.bf16.f32 "
        "{%0,%1,%2,%3}, {%4,%5,%6,%7}, {%8,%9}, {%0,%1,%2,%3};"
        : "+f"(c[0]), "+f"(c[1]), "+f"(c[2]), "+f"(c[3])
        : "r"(a[0]), "r"(a[1]), "r"(a[2]), "r"(a[3]), "r"(b[0]), "r"(b[1]));
}
__device__ __forceinline__ void mma16816h(float* c, const uint32_t* a, const uint32_t* b) {
    asm volatile(
        "mma.sync.aligned.m16n8k16.row.col.f32.f16.f16.f32 "
        "{%0,%1,%2,%3}, {%4,%5,%6,%7}, {%8,%9}, {%0,%1,%2,%3};"
        : "+f"(c[0]), "+f"(c[1]), "+f"(c[2]), "+f"(c[3])
        : "r"(a[0]), "r"(a[1]), "r"(a[2]), "r"(a[3]), "r"(b[0]), "r"(b[1]));
}
// pack two f32 -> bf16x2 (lo -> low half), round-to-nearest-even
__device__ __forceinline__ uint32_t cvtpack(float lo, float hi) {
    uint32_t r;
    asm("cvt.rn.bf16x2.f32 %0, %1, %2;" : "=r"(r) : "f"(hi), "f"(lo));
    return r;
}
// pack two f32 -> f16x2 (lo -> low half)
__device__ __forceinline__ uint32_t cvtpackh(float lo, float hi) {
    uint32_t r;
    asm("cvt.rn.f16x2.f32 %0, %1, %2;" : "=r"(r) : "f"(hi), "f"(lo));
    return r;
}
__device__ __forceinline__ float lo_f(uint32_t p) { return __uint_as_float(p << 16); }
__device__ __forceinline__ float hi_f(uint32_t p) { return __uint_as_float(p & 0xffff0000u); }

// ---------------------------------------------------------------------------
// Fused prep kernel:
// blocks [0,5120)      Wq/Wk transposes + bf16 hi/lo split
//        [5120,6144)   Wv transpose -> fp16
//        [6144,10240)  Wo transpose -> fp16
//        [10240,14336) x split (bf16 hi/lo + fp16)
//        [14336,14848) rope table
// ---------------------------------------------------------------------------
__global__ void __launch_bounds__(256)
prep_kernel(const float* __restrict__ Wq, const float* __restrict__ Wk,
            const float* __restrict__ Wv, const float* __restrict__ Wo,
            const float* __restrict__ x,
            __nv_bfloat16* __restrict__ wqkh, __nv_bfloat16* __restrict__ wqkl,
            __half* __restrict__ wv16, __half* __restrict__ wo16,
            __nv_bfloat16* __restrict__ xh, __nv_bfloat16* __restrict__ xl,
            __half* __restrict__ x16,
            float* __restrict__ ct, float* __restrict__ st)
{
    int bid = blockIdx.x;
    if (bid < 5120) {
        __shared__ float t[32][33];
        int id = bid;
        const float* W;
        __nv_bfloat16 *Th, *Tl;
        int N;
        if (id < 4096) { W = Wq; Th = wqkh;                   Tl = wqkl;                   N = NE;    }
        else           { W = Wk; Th = wqkh + (size_t)NE * NE; Tl = wqkl + (size_t)NE * NE; N = KVDIM; id -= 4096; }
        const int ntiles = N / 32;
        const int n0 = (id % ntiles) * 32;
        const int k0 = (id / ntiles) * 32;
        const int tx = threadIdx.x & 31, ty = threadIdx.x >> 5;
        #pragma unroll
        for (int i = 0; i < 4; i++)
            t[ty + i * 8][tx] = W[(size_t)(k0 + ty + i * 8) * N + n0 + tx];
        __syncthreads();
        #pragma unroll
        for (int i = 0; i < 4; i++) {
            int n = n0 + ty + i * 8, k = k0 + tx;
            float v = t[tx][ty + i * 8];
            __nv_bfloat16 h = __float2bfloat16(v);
            Th[(size_t)n * NE + k] = h;
            Tl[(size_t)n * NE + k] = __float2bfloat16(v - __bfloat162float(h));
        }
    } else if (bid < 6144) {
        // Wv transpose -> fp16
        __shared__ float t[32][33];
        int id = bid - 5120;
        const int n0 = (id & 15) * 32;
        const int k0 = (id >> 4) * 32;
        const int tx = threadIdx.x & 31, ty = threadIdx.x >> 5;
        #pragma unroll
        for (int i = 0; i < 4; i++)
            t[ty + i * 8][tx] = Wv[(size_t)(k0 + ty + i * 8) * KVDIM + n0 + tx];
        __syncthreads();
        #pragma unroll
        for (int i = 0; i < 4; i++) {
            int n = n0 + ty + i * 8, k = k0 + tx;
            wv16[(size_t)n * NE + k] = __float2half(t[tx][ty + i * 8]);
        }
    } else if (bid < 10240) {
        // Wo transpose -> fp16
        __shared__ float t[32][33];
        int id = bid - 6144;
        const int n0 = (id & 63) * 32;
        const int k0 = (id >> 6) * 32;
        const int tx = threadIdx.x & 31, ty = threadIdx.x >> 5;
        #pragma unroll
        for (int i = 0; i < 4; i++)
            t[ty + i * 8][tx] = Wo[(size_t)(k0 + ty + i * 8) * NE + n0 + tx];
        __syncthreads();
        #pragma unroll
        for (int i = 0; i < 4; i++) {
            int n = n0 + ty + i * 8, k = k0 + tx;
            wo16[(size_t)n * NE + k] = __float2half(t[tx][ty + i * 8]);
        }
    } else if (bid < 14336) {
        int i = (bid - 10240) * 256 + threadIdx.x;
        size_t base = (size_t)i * 8;
        float4 v0 = *(const float4*)(x + base);
        float4 v1 = *(const float4*)(x + base + 4);
        float vv[8] = {v0.x, v0.y, v0.z, v0.w, v1.x, v1.y, v1.z, v1.w};
        uint4 uh, ul, u16;
        uint32_t* ph = (uint32_t*)&uh;
        uint32_t* pl = (uint32_t*)&ul;
        uint32_t* p6 = (uint32_t*)&u16;
        #pragma unroll
        for (int j = 0; j < 4; j++) {
            uint32_t h = cvtpack(vv[2*j], vv[2*j+1]);
            ph[j] = h;
            pl[j] = cvtpack(vv[2*j] - lo_f(h), vv[2*j+1] - hi_f(h));
            p6[j] = cvtpackh(vv[2*j], vv[2*j+1]);
        }
        *(uint4*)(xh + base)  = uh;
        *(uint4*)(xl + base)  = ul;
        *(uint4*)(x16 + base) = u16;
    } else {
        int idx = (bid - 14336) * 256 + threadIdx.x;
        int t = idx >> 6;
        int i = idx & 63;
        double fr = exp(-((double)(2 * i) / (double)NE) * log(10000.0));
        float ff = (float)fr;
        float ang = __fmul_rn((float)t, ff);
        float s, c;
        sincosf(ang, &s, &c);
        ct[idx] = c;
        st[idx] = s;
    }
}

// ---------------------------------------------------------------------------
// GEMM core (QK regions): split-bf16 C = Ah@Bh^T + Ah@Bl^T + Al@Bh^T
// BM=256, BN=128, BK=64, 512 threads (4m x 4n warps, warp tile 64x32),
// 2-stage cp.async pipeline, ONE __syncthreads per stage. (R11-proven)
// ---------------------------------------------------------------------------
#define STG_BYTES 98304
#define GEMM_SMEM (2*STG_BYTES + 1024)

__device__ __forceinline__ void gemm_core(
    const __nv_bfloat16* __restrict__ Ah, const __nv_bfloat16* __restrict__ Al,
    const __nv_bfloat16* __restrict__ BTh, const __nv_bfloat16* __restrict__ BTl,
    int K, int m0, int n0, uint32_t sb, int tid, float c[4][4][4])
{
    const int lane = tid & 31;
    const int wm   = (tid >> 5) >> 2;
    const int wn   = (tid >> 5) & 3;
    const int nstage = K / 64;

    #pragma unroll
    for (int im = 0; im < 4; im++)
        #pragma unroll
        for (int in = 0; in < 4; in++)
            #pragma unroll
            for (int j = 0; j < 4; j++) c[im][in][j] = 0.f;

    auto load_stage = [&](int s) {
        const int k0 = s * 64;
        const uint32_t stg = sb + (uint32_t)(s & 1) * STG_BYTES;
        #pragma unroll
        for (int i = 0; i < 12; i++) {
            int idx = tid + (i << 9);
            if (idx < 4096) {
                int mat = idx >> 11;
                int row = (idx >> 3) & 255;
                int q   = idx & 7;
                const __nv_bfloat16* src =
                    (mat ? Al : Ah) + (size_t)(m0 + row) * K + k0 + q * 8;
                cp16(stg + mat * 32768 + sw128((uint32_t)(row * 128 + q * 16)), src);
            } else {
                int rel = idx - 4096;
                int mat = rel >> 10;
                int row = (rel >> 3) & 127;
                int q   = rel & 7;
                const __nv_bfloat16* src =
                    (mat ? BTl : BTh) + (size_t)(n0 + row) * K + k0 + q * 8;
                cp16(stg + 65536 + mat * 16384 + sw128((uint32_t)(row * 128 + q * 16)), src);
            }
        }
    };

    load_stage(0);
    asm volatile("cp.async.commit_group;" ::: "memory");

    const int aRow  = (lane & 15);
    const int aKoff = (lane >> 4) << 4;
    const int bRow  = (lane & 7) + ((lane >> 4) << 3);
    const int bKoff = ((lane >> 3) & 1) << 4;

    for (int s = 0; s < nstage; s++) {
        asm volatile("cp.async.wait_group 0;" ::: "memory");
        __syncthreads();
        if (s + 1 < nstage) {
            load_stage(s + 1);
            asm volatile("cp.async.commit_group;" ::: "memory");
        }

        const uint32_t ab = sb + (uint32_t)(s & 1) * STG_BYTES;

        #pragma unroll
        for (int kk = 0; kk < 4; kk++) {
            const int kb = kk * 32;
            uint32_t b_h[8], b_l[8];
            #pragma unroll
            for (int ib = 0; ib < 2; ib++) {
                uint32_t off = sw128((uint32_t)((wn * 32 + ib * 16 + bRow) * 128 + kb + bKoff));
                ldsm4(&b_h[ib * 4], ab + 65536 + off);
                ldsm4(&b_l[ib * 4], ab + 81920 + off);
            }
            #pragma unroll
            for (int im = 0; im < 4; im++) {
                uint32_t a_h[4], a_l[4];
                uint32_t off = sw128((uint32_t)((wm * 64 + im * 16 + aRow) * 128 + kb + aKoff));
                ldsm4(a_h, ab + off);
                ldsm4(a_l, ab + 32768 + off);
                #pragma unroll
                for (int in = 0; in < 4; in++) {
                    const uint32_t* bh = &b_h[(in >> 1) * 4 + (in & 1) * 2];
                    const uint32_t* bl = &b_l[(in >> 1) * 4 + (in & 1) * 2];
                    mma16816(c[im][in], a_h, bh);
                    mma16816(c[im][in], a_l, bh);
                    mma16816(c[im][in], a_h, bl);
                }
            }
        }
    }
    __syncthreads();
}

// fp16 single-term core (V region / O-proj): C = A16 @ BT16^T
__device__ __forceinline__ void gemm_core_h(
    const __half* __restrict__ A, const __half* __restrict__ BT,
    int K, int m0, int n0, uint32_t sb, int tid, uint32_t stg_bytes, float c[4][4][4])
{
    const int lane = tid & 31;
    const int wm   = (tid >> 5) >> 2;
    const int wn   = (tid >> 5) & 3;
    const int nstage = K / 64;

    #pragma unroll
    for (int im = 0; im < 4; im++)
        #pragma unroll
        for (int in = 0; in < 4; in++)
            #pragma unroll
            for (int j = 0; j < 4; j++) c[im][in][j] = 0.f;

    auto load_stage = [&](int s) {
        const int k0 = s * 64;
        const uint32_t stg = sb + (uint32_t)(s & 1) * stg_bytes;
        #pragma unroll
        for (int i = 0; i < 6; i++) {
            int idx = tid + (i << 9);
            if (idx < 2048) {
                int row = idx >> 3;
                int q   = idx & 7;
                cp16(stg + sw128((uint32_t)(row * 128 + q * 16)),
                     A + (size_t)(m0 + row) * K + k0 + q * 8);
            } else {
                int rel = idx - 2048;
                int row = rel >> 3;
                int q   = rel & 7;
                cp16(stg + 32768 + sw128((uint32_t)(row * 128 + q * 16)),
                     BT + (size_t)(n0 + row) * K + k0 + q * 8);
            }
        }
    };

    load_stage(0);
    asm volatile("cp.async.commit_group;" ::: "memory");

    const int aRow  = (lane & 15);
    const int aKoff = (lane >> 4) << 4;
    const int bRow  = (lane & 7) + ((lane >> 4) << 3);
    const int bKoff = ((lane >> 3) & 1) << 4;

    for (int s = 0; s < nstage; s++) {
        asm volatile("cp.async.wait_group 0;" ::: "memory");
        __syncthreads();
        if (s + 1 < nstage) {
            load_stage(s + 1);
            asm volatile("cp.async.commit_group;" ::: "memory");
        }

        const uint32_t ab = sb + (uint32_t)(s & 1) * stg_bytes;

        #pragma unroll
        for (int kk = 0; kk < 4; kk++) {
            const int kb = kk * 32;
            uint32_t b_f[8];
            #pragma unroll
            for (int ib = 0; ib < 2; ib++) {
                uint32_t off = sw128((uint32_t)((wn * 32 + ib * 16 + bRow) * 128 + kb + bKoff));
                ldsm4(&b_f[ib * 4], ab + 32768 + off);
            }
            #pragma unroll
            for (int im = 0; im < 4; im++) {
                uint32_t a_f[4];
                uint32_t off = sw128((uint32_t)((wm * 64 + im * 16 + aRow) * 128 + kb + aKoff));
                ldsm4(a_f, ab + off);
                #pragma unroll
                for (int in = 0; in < 4; in++)
                    mma16816h(c[im][in], a_f, &b_f[(in >> 1) * 4 + (in & 1) * 2]);
            }
        }
    }
    __syncthreads();
}

// ---------------------------------------------------------------------------
// QKV GEMM, persistent work-stealing over 384 tiles:
// tiles [0,320) = QK split-bf16 (+RoPE epilogue), [320,384) = V fp16.
// 148 CTAs, 512 threads.
// ---------------------------------------------------------------------------
__global__ void __launch_bounds__(512, 1)
gemm_qkv_kernel(const __nv_bfloat16* __restrict__ Ah, const __nv_bfloat16* __restrict__ Al,
                const __nv_bfloat16* __restrict__ BTh, const __nv_bfloat16* __restrict__ BTl,
                const __half* __restrict__ x16, const __half* __restrict__ wv16,
                const float* __restrict__ bq, const float* __restrict__ bk,
                const float* __restrict__ bv,
                const float* __restrict__ ct, const float* __restrict__ st,
                __nv_bfloat16* __restrict__ qr, __nv_bfloat16* __restrict__ kr,
                __half* __restrict__ v16, uint32_t* __restrict__ ctr)
{
    extern __shared__ char dsm[];
    char* smbase = (char*)(((uintptr_t)dsm + 1023) & ~(uintptr_t)1023);
    const uint32_t sb = smem_u32(smbase);
    const int tid  = threadIdx.x;
    const int lane = tid & 31;
    const int wm   = (tid >> 5) >> 2;
    const int wn   = (tid >> 5) & 3;

    __shared__ int s_tile;

    for (;;) {
        if (tid == 0) s_tile = (int)atomicAdd(ctr, 1u);
        __syncthreads();
        const int lin = s_tile;
        if (lin >= 384) return;

        int colt, rowt, region;
        if (lin < 320) {
            colt = lin % 20; rowt = lin / 20;
            region = (colt >= 16) ? 1 : 0;
        } else {
            int v = lin - 320;
            colt = 20 + (v & 3); rowt = v >> 2; region = 2;
        }
        const int m0 = rowt * 256;
        const int n0 = colt * 128;

        float c[4][4][4];
        if (region == 2) {
            gemm_core_h(x16, wv16, NE, m0, n0 - NQK, sb, tid, STG_BYTES, c);
        } else {
            gemm_core(Ah, Al, BTh, BTl, NE, m0, n0, sb, tid, c);
        }

        #pragma unroll
        for (int im = 0; im < 4; im++) {
            const int r0 = m0 + wm * 64 + im * 16 + (lane >> 2);
            const int b  = r0 >> 11;
            const int t  = r0 & 2047;
            #pragma unroll
            for (int in = 0; in < 4; in++) {
                const int cc = n0 + wn * 32 + in * 8 + ((lane & 3) << 1);
                float b0, b1;
                if (region == 0)      { b0 = bq[cc];       b1 = bq[cc + 1]; }
                else if (region == 1) { b0 = bk[cc - NE];  b1 = bk[cc - NE + 1]; }
                else                  { b0 = bv[cc - NQK]; b1 = bv[cc - NQK + 1]; }
                float v0 = c[im][in][0] + b0, v1 = c[im][in][1] + b1;   // row t
                float v2 = c[im][in][2] + b0, v3 = c[im][in][3] + b1;   // row t+8
                const int dloc = cc & 127;
                if (region <= 1) {
                    const int i  = dloc >> 1;
                    float c0 = ct[t * 64 + i],       s0 = st[t * 64 + i];
                    float c2 = ct[(t + 8) * 64 + i], s2 = st[(t + 8) * 64 + i];
                    uint32_t p0 = cvtpack(v0 * c0 - v1 * s0, v0 * s0 + v1 * c0);
                    uint32_t p2 = cvtpack(v2 * c2 - v3 * s2, v2 * s2 + v3 * c2);
                    if (region == 0) {
                        const int h = cc >> 7;
                        size_t dst = ((size_t)((b * NH + h) * TT + t)) * HD + dloc;
                        *(uint32_t*)(qr + dst)          = p0;
                        *(uint32_t*)(qr + dst + 8 * HD) = p2;
                    } else {
                        const int h = (cc - NE) >> 7;
                        size_t dst = ((size_t)((b * NKV + h) * TT + t)) * HD + dloc;
                        *(uint32_t*)(kr + dst)          = p0;
                        *(uint32_t*)(kr + dst + 8 * HD) = p2;
                    }
                } else {
                    const int h = (cc - NQK) >> 7;
                    size_t dst = ((size_t)((b * NKV + h) * TT + t)) * HD + dloc;
                    *(uint32_t*)(v16 + dst)          = cvtpackh(v0, v1);
                    *(uint32_t*)(v16 + dst + 8 * HD) = cvtpackh(v2, v3);
                }
            }
        }
        // gemm cores end with __syncthreads(); all threads have consumed s_tile
        // long before tid 0 rewrites it next iteration.
    }
}

// ---------------------------------------------------------------------------
// Output projection GEMM, persistent work-stealing over 256 tiles:
// fp16 x fp16 single-term (+bias) -> fp32 out. 148 CTAs.
// ---------------------------------------------------------------------------
#define OSTG_BYTES 49152
#define GEMMO_SMEM (2*OSTG_BYTES + 1024)

__global__ void __launch_bounds__(512, 1)
gemm_out_kernel(const __half* __restrict__ A, const __half* __restrict__ BT,
                const float* __restrict__ bias, float* __restrict__ C,
                uint32_t* __restrict__ ctr)
{
    extern __shared__ char dsm[];
    char* smbase = (char*)(((uintptr_t)dsm + 1023) & ~(uintptr_t)1023);
    const uint32_t sb = smem_u32(smbase);
    const int tid  = threadIdx.x;
    const int lane = tid & 31;
    const int wm   = (tid >> 5) >> 2;
    const int wn   = (tid >> 5) & 3;

    __shared__ int s_tile;

    for (;;) {
        if (tid == 0) s_tile = (int)atomicAdd(ctr, 1u);
        __syncthreads();
        const int lin = s_tile;
        if (lin >= 256) return;
        const int m0 = (lin >> 4) * 256;
        const int n0 = (lin & 15) * 128;

        float c[4][4][4];
        gemm_core_h(A, BT, NE, m0, n0, sb, tid, OSTG_BYTES, c);

        #pragma unroll
        for (int im = 0; im < 4; im++) {
            const int r0 = m0 + wm * 64 + im * 16 + (lane >> 2);
            #pragma unroll
            for (int in = 0; in < 4; in++) {
                const int cc = n0 + wn * 32 + in * 8 + ((lane & 3) << 1);
                float2 bb = *(const float2*)&bias[cc];
                float2 o0, o1;
                o0.x = c[im][in][0] + bb.x;  o0.y = c[im][in][1] + bb.y;
                o1.x = c[im][in][2] + bb.x;  o1.y = c[im][in][3] + bb.y;
                *(float2*)&C[(size_t)r0 * NE + cc]       = o0;
                *(float2*)&C[(size_t)(r0 + 8) * NE + cc] = o1;
            }
        }
    }
}

// ---------------------------------------------------------------------------
// Flash attention (causal, GQA). S=QK^T on bf16 mma (reference-exact);
// AV on fp16 P x fp16 V single term. BM=64, BN=64, 128 threads/4 warps,
// 3 CTAs/SM. Ring-2 {K,V} buffers, ONE sync per tile, prefetch AFTER sync.
// Q borrows buf1's K slot for tile 0. Epilogue writes fp16 o16.
// ---------------------------------------------------------------------------
#define AT_RS 272
#define AT_T64 (64 * AT_RS)
#define ATT_SMEM (4 * AT_T64 + 1024)

__global__ void __launch_bounds__(128, 3)
attn_mma_kernel(const __nv_bfloat16* __restrict__ qr, const __nv_bfloat16* __restrict__ kr,
                const __half* __restrict__ v16, __half* __restrict__ o16)
{
    extern __shared__ char dsm2[];
    char* smb = (char*)(((uintptr_t)dsm2 + 1023) & ~(uintptr_t)1023);
    const uint32_t sb = smem_u32(smb);

    const int tid  = threadIdx.x;
    const int lane = tid & 31;
    const int w    = tid >> 5;                              // 0..3
    const int mtb  = (int)gridDim.x - 1 - (int)blockIdx.x;  // heavy blocks first
    const int h    = blockIdx.y, b = blockIdx.z;
    const int m0   = mtb * 64;
    const int kv   = h >> 2;
    const int ntile = mtb + 1;

    const __nv_bfloat16* qg = qr  + ((size_t)(b * NH + h) * TT + m0) * HD;
    const __nv_bfloat16* kg = kr  + ((size_t)(b * NKV + kv) * TT) * HD;
    const __half*        vg = v16 + ((size_t)(b * NKV + kv) * TT) * HD;

    auto toff = [&](int buf, int which) -> uint32_t {
        return sb + (uint32_t)AT_T64 * (buf * 2 + which);
    };
    const uint32_t Q0 = toff(1, 0);
    auto load64 = [&](uint32_t dst, const void* srcbase, int tile) {
        const char* src = (const char*)srcbase + (size_t)tile * 64 * HD * 2;
        #pragma unroll
        for (int i = 0; i < 8; i++) {
            int idx = tid + i * 128;
            int row = idx >> 4, cq = idx & 15;
            cp16(dst + (uint32_t)(row * AT_RS + cq * 16), src + (size_t)row * HD * 2 + cq * 16);
        }
    };

    load64(Q0, qg, 0);
    load64(toff(0, 0), kg, 0);
    load64(toff(0, 1), vg, 0);
    asm volatile("cp.async.commit_group;" ::: "memory");

    uint32_t qf[8][4];
    float ov[16][4];
    #pragma unroll
    for (int n = 0; n < 16; n++) { ov[n][0] = ov[n][1] = ov[n][2] = ov[n][3] = 0.f; }
    float m_lo = -1e30f, m_hi = -1e30f, l_lo = 0.f, l_hi = 0.f;

    const int aRow = lane & 15;
    const int aK   = (lane >> 4) << 4;
    const int bRow = (lane & 7) + ((lane >> 4) << 3);
    const int bK   = ((lane >> 3) & 1) << 4;
    const int vRow = (lane & 7) + (((lane >> 3) & 1) << 3);
    const int vC   = (lane >> 4) << 4;

    for (int jt = 0; jt < ntile; jt++) {
        asm volatile("cp.async.wait_group 0;" ::: "memory");
        __syncthreads();
        if (jt == 0) {
            #pragma unroll
            for (int kt = 0; kt < 8; kt++)
                ldsm4(qf[kt], Q0 + (uint32_t)((w * 16 + aRow) * AT_RS + kt * 32 + aK));
            __syncthreads();
        }
        if (jt + 1 < ntile) {
            int nb = (jt + 1) & 1;
            load64(toff(nb, 0), kg, jt + 1);
            load64(toff(nb, 1), vg, jt + 1);
            asm volatile("cp.async.commit_group;" ::: "memory");
        }

        const int cbuf = jt & 1;
        const uint32_t kb = toff(cbuf, 0);
        const uint32_t vb = toff(cbuf, 1);

        // ---- S = Q @ K^T (bf16, reference-exact inputs) ----
        float sc[8][4];
        #pragma unroll
        for (int j = 0; j < 8; j++) { sc[j][0] = sc[j][1] = sc[j][2] = sc[j][3] = 0.f; }

        #pragma unroll
        for (int kt = 0; kt < 8; kt++) {
            #pragma unroll
            for (int ib = 0; ib < 4; ib++) {
                uint32_t bf[4];
                ldsm4(bf, kb + (uint32_t)((ib * 16 + bRow) * AT_RS + kt * 32 + bK));
                mma16816(sc[2 * ib],     qf[kt], bf);
                mma16816(sc[2 * ib + 1], qf[kt], bf + 2);
            }
        }

        // ---- causal mask (diagonal tile only) ----
        if (jt == ntile - 1) {
            const int rl = w * 16 + (lane >> 2);
            #pragma unroll
            for (int j = 0; j < 8; j++) {
                int gn = j * 8 + ((lane & 3) << 1);
                if (gn     > rl)     sc[j][0] = -1e30f;
                if (gn + 1 > rl)     sc[j][1] = -1e30f;
                if (gn     > rl + 8) sc[j][2] = -1e30f;
                if (gn + 1 > rl + 8) sc[j][3] = -1e30f;
            }
        }

        // ---- online softmax ----
        float vlo = -1e30f, vhi = -1e30f;
        #pragma unroll
        for (int j = 0; j < 8; j++) {
            vlo = fmaxf(vlo, fmaxf(sc[j][0], sc[j][1]));
            vhi = fmaxf(vhi, fmaxf(sc[j][2], sc[j][3]));
        }
        vlo = fmaxf(vlo, __shfl_xor_sync(0xffffffffu, vlo, 1));
        vlo = fmaxf(vlo, __shfl_xor_sync(0xffffffffu, vlo, 2));
        vhi = fmaxf(vhi, __shfl_xor_sync(0xffffffffu, vhi, 1));
        vhi = fmaxf(vhi, __shfl_xor_sync(0xffffffffu, vhi, 2));
        float mn_lo = fmaxf(m_lo, vlo), mn_hi = fmaxf(m_hi, vhi);
        float al_lo = __expf(m_lo - mn_lo), al_hi = __expf(m_hi - mn_hi);
        m_lo = mn_lo; m_hi = mn_hi;
        l_lo *= al_lo; l_hi *= al_hi;
        #pragma unroll
        for (int n = 0; n < 16; n++) {
            ov[n][0] *= al_lo; ov[n][1] *= al_lo;
            ov[n][2] *= al_hi; ov[n][3] *= al_hi;
        }

        uint32_t ph[8][2];
        #pragma unroll
        for (int j = 0; j < 8; j++) {
            float p0 = __expf(sc[j][0] - m_lo), p1 = __expf(sc[j][1] - m_lo);
            float p2 = __expf(sc[j][2] - m_hi), p3 = __expf(sc[j][3] - m_hi);
            l_lo += p0 + p1;  l_hi += p2 + p3;
            ph[j][0] = cvtpackh(p0, p1);
            ph[j][1] = cvtpackh(p2, p3);
        }

        // ---- O += P @ V  (fp16 x fp16, single term) ----
        #pragma unroll
        for (int kt = 0; kt < 4; kt++) {
            uint32_t ah[4] = { ph[2*kt][0], ph[2*kt][1], ph[2*kt+1][0], ph[2*kt+1][1] };
            #pragma unroll
            for (int np = 0; np < 4; np++) {
                uint32_t base = (uint32_t)((kt * 16 + vRow) * AT_RS + np * 64 + vC);
                uint32_t bh0[4], bh1[4];
                ldsm4t(bh0, vb + base);
                ldsm4t(bh1, vb + base + 32);
                mma16816h(ov[np*4+0], ah, bh0);
                mma16816h(ov[np*4+1], ah, bh0 + 2);
                mma16816h(ov[np*4+2], ah, bh1);
                mma16816h(ov[np*4+3], ah, bh1 + 2);
            }
        }
    }

    // ---- epilogue: normalize, write fp16 o16 ----
    l_lo += __shfl_xor_sync(0xffffffffu, l_lo, 1);
    l_lo += __shfl_xor_sync(0xffffffffu, l_lo, 2);
    l_hi += __shfl_xor_sync(0xffffffffu, l_hi, 1);
    l_hi += __shfl_xor_sync(0xffffffffu, l_hi, 2);
    const float inv_lo = 0.022097086912079608f / l_lo;
    const float inv_hi = 0.022097086912079608f / l_hi;
    const int rlo = m0 + w * 16 + (lane >> 2);
    size_t base = ((size_t)(b * TT) + rlo) * NE + h * HD;
    #pragma unroll
    for (int n = 0; n < 16; n++) {
        int d = n * 8 + ((lane & 3) << 1);
        *(uint32_t*)(o16 + base + d)          = cvtpackh(ov[n][0] * inv_lo, ov[n][1] * inv_lo);
        *(uint32_t*)(o16 + base + 8 * NE + d) = cvtpackh(ov[n][2] * inv_hi, ov[n][3] * inv_hi);
    }
}

// ---------------------------------------------------------------------------
// launch
// ---------------------------------------------------------------------------
extern "C" void kernel_launch(void* const* d_in, const int* in_sizes, int n_in,
                              void* d_out, int out_size)
{
    const float* x  = (const float*)d_in[0];
    const float* Wq = (const float*)d_in[1];
    const float* bq = (const float*)d_in[2];
    const float* Wk = (const float*)d_in[3];
    const float* bk = (const float*)d_in[4];
    const float* Wv = (const float*)d_in[5];
    const float* bv = (const float*)d_in[6];
    const float* Wo = (const float*)d_in[7];
    const float* bo = (const float*)d_in[8];
    float* out = (float*)d_out;

    float *ct, *st;
    __nv_bfloat16 *qr, *kr;
    __half *v16, *o16, *x16, *wv16, *wo16;
    __nv_bfloat16 *xh, *xl;
    __nv_bfloat16 *wqkh, *wqkl;
    uint32_t* ctr;
    cudaGetSymbolAddress((void**)&ct, g_cos);
    cudaGetSymbolAddress((void**)&st, g_sin);
    cudaGetSymbolAddress((void**)&qr, g_qr);
    cudaGetSymbolAddress((void**)&kr, g_kr);
    cudaGetSymbolAddress((void**)&v16, g_v16);
    cudaGetSymbolAddress((void**)&o16, g_o16);
    cudaGetSymbolAddress((void**)&x16, g_x16);
    cudaGetSymbolAddress((void**)&xh, g_xh);
    cudaGetSymbolAddress((void**)&xl, g_xl);
    cudaGetSymbolAddress((void**)&wqkh, g_wqkh);
    cudaGetSymbolAddress((void**)&wqkl, g_wqkl);
    cudaGetSymbolAddress((void**)&wv16, g_wv16);
    cudaGetSymbolAddress((void**)&wo16, g_wo16);
    cudaGetSymbolAddress((void**)&ctr, g_ctr);

    cudaFuncSetAttribute(gemm_qkv_kernel, cudaFuncAttributeMaxDynamicSharedMemorySize, GEMM_SMEM);
    cudaFuncSetAttribute(gemm_out_kernel, cudaFuncAttributeMaxDynamicSharedMemorySize, GEMMO_SMEM);
    cudaFuncSetAttribute(attn_mma_kernel, cudaFuncAttributeMaxDynamicSharedMemorySize, ATT_SMEM);

    // zero work-steal counters (graph-capturable)
    cudaMemsetAsync(ctr, 0, 2 * sizeof(uint32_t));

    // fused prep (1 launch)
    prep_kernel<<<14848, 256>>>(Wq, Wk, Wv, Wo, x, wqkh, wqkl, wv16, wo16,
                                xh, xl, x16, ct, st);

    // fused QKV projection: persistent 148 CTAs, QK tiles first, V tiles last
    gemm_qkv_kernel<<<NSM, 512, GEMM_SMEM>>>(
        xh, xl, wqkh, wqkl, x16, wv16, bq, bk, bv, ct, st, qr, kr, v16, ctr);

    // attention (writes fp16 o16); 3 CTAs/SM
    {
        dim3 grid(TT / 64, NH, BB);
        attn_mma_kernel<<<grid, 128, ATT_SMEM>>>(qr, kr, v16, o16);
    }

    // output projection: fp16 single-term, persistent 148 CTAs
    gemm_out_kernel<<<NSM, 512, GEMMO_SMEM>>>(o16, wo16, bo, out, ctr + 1);
}

// round 17
// speedup vs baseline: 1.0758x; 1.0649x over previous
#include <cuda_runtime.h>
#include <cuda_bf16.h>
#include <cuda_fp16.h>
#include <cstdint>
#include <cmath>

// ---------------------------------------------------------------------------
// Problem constants (fixed shapes)
// ---------------------------------------------------------------------------
#define BB 2
#define TT 2048
#define NE 2048          // N_EMBED
#define NH 16            // N_HEAD
#define NKV 4            // N_KV_HEAD
#define HD 128           // HEAD_DIM
#define MROWS (BB*TT)    // 4096
#define KVDIM (NKV*HD)   // 512
#define NQK (NE + KVDIM)      // 2560
#define NSM 148

// ---------------------------------------------------------------------------
// Scratch (static device globals; no allocations allowed)
// ---------------------------------------------------------------------------
__device__ __nv_bfloat16 g_qr[(size_t)BB * NH * TT * HD];   // rope(q) bf16 [B,H,T,D]
__device__ __nv_bfloat16 g_kr[(size_t)BB * NKV * TT * HD];  // rope(k) bf16 [B,KV,T,D]
__device__ __half        g_v16[(size_t)BB * NKV * TT * HD]; // v fp16 [B,KV,T,D]
__device__ __half        g_o16[(size_t)MROWS * NE];         // attn out fp16
__device__ float g_cos[TT * (HD/2)];
__device__ float g_sin[TT * (HD/2)];
__device__ uint32_t g_ctr[2];                               // work-steal counters

// operands for tensor-core GEMMs
__device__ __nv_bfloat16 g_xh[(size_t)MROWS * NE];
__device__ __nv_bfloat16 g_xl[(size_t)MROWS * NE];
__device__ __half        g_x16[(size_t)MROWS * NE];         // x fp16 (for V proj)
// packed transposed weights [N][K] hi/lo: rows 0..2047 Wq^T, 2048..2559 Wk^T
__device__ __nv_bfloat16 g_wqkh[(size_t)NQK * NE];
__device__ __nv_bfloat16 g_wqkl[(size_t)NQK * NE];
__device__ __half        g_wv16[(size_t)KVDIM * NE];        // Wv^T fp16 [N][K]
__device__ __half        g_wo16[(size_t)NE * NE];           // Wo^T fp16 [N][K]

// ---------------------------------------------------------------------------
// Helpers (baseline PTX only — no sm_103a-suffixed features)
// ---------------------------------------------------------------------------
__device__ __forceinline__ uint32_t smem_u32(const void* p) {
    uint32_t a;
    asm("{ .reg .u64 t; cvta.to.shared.u64 t, %1; cvt.u32.u64 %0, t; }" : "=r"(a) : "l"(p));
    return a;
}
__device__ __forceinline__ uint32_t sw128(uint32_t off) {
    return off ^ ((off >> 3) & 0x70);
}
__device__ __forceinline__ void cp16(uint32_t dst, const void* src) {
    asm volatile("cp.async.cg.shared.global [%0], [%1], 16;" :: "r"(dst), "l"(src) : "memory");
}
__device__ __forceinline__ void ldsm4(uint32_t* r, uint32_t addr) {
    asm volatile("ldmatrix.sync.aligned.m8n8.x4.shared.b16 {%0,%1,%2,%3}, [%4];"
                 : "=r"(r[0]), "=r"(r[1]), "=r"(r[2]), "=r"(r[3]) : "r"(addr));
}
__device__ __forceinline__ void ldsm4t(uint32_t* r, uint32_t addr) {
    asm volatile("ldmatrix.sync.aligned.m8n8.x4.trans.shared.b16 {%0,%1,%2,%3}, [%4];"
                 : "=r"(r[0]), "=r"(r[1]), "=r"(r[2]), "=r"(r[3]) : "r"(addr));
}
__device__ __forceinline__ void mma16816(float* c, const uint32_t* a, const uint32_t* b) {
    asm volatile(
        "mma.sync.aligned.m16n8k16.row.col.f32.bf16.bf16.f32 "
        "{%0,%1,%2,%3}, {%4,%5,%6,%7}, {%8,%9}, {%0,%1,%2,%3};"
        : "+f"(c[0]), "+f"(c[1]), "+f"(c[2]), "+f"(c[3])
        : "r"(a[0]), "r"(a[1]), "r"(a[2]), "r"(a[3]), "r"(b[0]), "r"(b[1]));
}
__device__ __forceinline__ void mma16816h(float* c, const uint32_t* a, const uint32_t* b) {
    asm volatile(
        "mma.sync.aligned.m16n8k16.row.col.f32.f16.f16.f32 "
        "{%0,%1,%2,%3}, {%4,%5,%6,%7}, {%8,%9}, {%0,%1,%2,%3};"
        : "+f"(c[0]), "+f"(c[1]), "+f"(c[2]), "+f"(c[3])
        : "r"(a[0]), "r"(a[1]), "r"(a[2]), "r"(a[3]), "r"(b[0]), "r"(b[1]));
}
__device__ __forceinline__ uint32_t cvtpack(float lo, float hi) {
    uint32_t r;
    asm("cvt.rn.bf16x2.f32 %0, %1, %2;" : "=r"(r) : "f"(hi), "f"(lo));
    return r;
}
__device__ __forceinline__ uint32_t cvtpackh(float lo, float hi) {
    uint32_t r;
    asm("cvt.rn.f16x2.f32 %0, %1, %2;" : "=r"(r) : "f"(hi), "f"(lo));
    return r;
}
__device__ __forceinline__ float lo_f(uint32_t p) { return __uint_as_float(p << 16); }
__device__ __forceinline__ float hi_f(uint32_t p) { return __uint_as_float(p & 0xffff0000u); }

// ---------------------------------------------------------------------------
// Fused prep kernel (unchanged from R16)
// ---------------------------------------------------------------------------
__global__ void __launch_bounds__(256)
prep_kernel(const float* __restrict__ Wq, const float* __restrict__ Wk,
            const float* __restrict__ Wv, const float* __restrict__ Wo,
            const float* __restrict__ x,
            __nv_bfloat16* __restrict__ wqkh, __nv_bfloat16* __restrict__ wqkl,
            __half* __restrict__ wv16, __half* __restrict__ wo16,
            __nv_bfloat16* __restrict__ xh, __nv_bfloat16* __restrict__ xl,
            __half* __restrict__ x16,
            float* __restrict__ ct, float* __restrict__ st)
{
    int bid = blockIdx.x;
    if (bid < 5120) {
        __shared__ float t[32][33];
        int id = bid;
        const float* W;
        __nv_bfloat16 *Th, *Tl;
        int N;
        if (id < 4096) { W = Wq; Th = wqkh;                   Tl = wqkl;                   N = NE;    }
        else           { W = Wk; Th = wqkh + (size_t)NE * NE; Tl = wqkl + (size_t)NE * NE; N = KVDIM; id -= 4096; }
        const int ntiles = N / 32;
        const int n0 = (id % ntiles) * 32;
        const int k0 = (id / ntiles) * 32;
        const int tx = threadIdx.x & 31, ty = threadIdx.x >> 5;
        #pragma unroll
        for (int i = 0; i < 4; i++)
            t[ty + i * 8][tx] = W[(size_t)(k0 + ty + i * 8) * N + n0 + tx];
        __syncthreads();
        #pragma unroll
        for (int i = 0; i < 4; i++) {
            int n = n0 + ty + i * 8, k = k0 + tx;
            float v = t[tx][ty + i * 8];
            __nv_bfloat16 h = __float2bfloat16(v);
            Th[(size_t)n * NE + k] = h;
            Tl[(size_t)n * NE + k] = __float2bfloat16(v - __bfloat162float(h));
        }
    } else if (bid < 6144) {
        __shared__ float t[32][33];
        int id = bid - 5120;
        const int n0 = (id & 15) * 32;
        const int k0 = (id >> 4) * 32;
        const int tx = threadIdx.x & 31, ty = threadIdx.x >> 5;
        #pragma unroll
        for (int i = 0; i < 4; i++)
            t[ty + i * 8][tx] = Wv[(size_t)(k0 + ty + i * 8) * KVDIM + n0 + tx];
        __syncthreads();
        #pragma unroll
        for (int i = 0; i < 4; i++) {
            int n = n0 + ty + i * 8, k = k0 + tx;
            wv16[(size_t)n * NE + k] = __float2half(t[tx][ty + i * 8]);
        }
    } else if (bid < 10240) {
        __shared__ float t[32][33];
        int id = bid - 6144;
        const int n0 = (id & 63) * 32;
        const int k0 = (id >> 6) * 32;
        const int tx = threadIdx.x & 31, ty = threadIdx.x >> 5;
        #pragma unroll
        for (int i = 0; i < 4; i++)
            t[ty + i * 8][tx] = Wo[(size_t)(k0 + ty + i * 8) * NE + n0 + tx];
        __syncthreads();
        #pragma unroll
        for (int i = 0; i < 4; i++) {
            int n = n0 + ty + i * 8, k = k0 + tx;
            wo16[(size_t)n * NE + k] = __float2half(t[tx][ty + i * 8]);
        }
    } else if (bid < 14336) {
        int i = (bid - 10240) * 256 + threadIdx.x;
        size_t base = (size_t)i * 8;
        float4 v0 = *(const float4*)(x + base);
        float4 v1 = *(const float4*)(x + base + 4);
        float vv[8] = {v0.x, v0.y, v0.z, v0.w, v1.x, v1.y, v1.z, v1.w};
        uint4 uh, ul, u16;
        uint32_t* ph = (uint32_t*)&uh;
        uint32_t* pl = (uint32_t*)&ul;
        uint32_t* p6 = (uint32_t*)&u16;
        #pragma unroll
        for (int j = 0; j < 4; j++) {
            uint32_t h = cvtpack(vv[2*j], vv[2*j+1]);
            ph[j] = h;
            pl[j] = cvtpack(vv[2*j] - lo_f(h), vv[2*j+1] - hi_f(h));
            p6[j] = cvtpackh(vv[2*j], vv[2*j+1]);
        }
        *(uint4*)(xh + base)  = uh;
        *(uint4*)(xl + base)  = ul;
        *(uint4*)(x16 + base) = u16;
    } else {
        int idx = (bid - 14336) * 256 + threadIdx.x;
        int t = idx >> 6;
        int i = idx & 63;
        double fr = exp(-((double)(2 * i) / (double)NE) * log(10000.0));
        float ff = (float)fr;
        float ang = __fmul_rn((float)t, ff);
        float s, c;
        sincosf(ang, &s, &c);
        ct[idx] = c;
        st[idx] = s;
    }
}

// ---------------------------------------------------------------------------
// QK core: split-bf16, BM=128, BN=128, BK=64, 512 threads (4m x 4n warps,
// warp tile 32x32), ring-3 smem, TWO cp.async groups in flight.
// Stage: Ah@0 | Al@16K | Bh@32K | Bl@48K (64KB)
// ---------------------------------------------------------------------------
#define QK_STG 65536
#define GEMM_SMEM (3*QK_STG + 1024)

__device__ __forceinline__ void gemm_core(
    const __nv_bfloat16* __restrict__ Ah, const __nv_bfloat16* __restrict__ Al,
    const __nv_bfloat16* __restrict__ BTh, const __nv_bfloat16* __restrict__ BTl,
    int K, int m0, int n0, uint32_t sb, int tid, float c[2][4][4])
{
    const int lane = tid & 31;
    const int wm   = (tid >> 5) >> 2;   // 0..3 (32 rows each)
    const int wn   = (tid >> 5) & 3;    // 0..3 (32 cols each)
    const int nstage = K / 64;

    #pragma unroll
    for (int im = 0; im < 2; im++)
        #pragma unroll
        for (int in = 0; in < 4; in++)
            #pragma unroll
            for (int j = 0; j < 4; j++) c[im][in][j] = 0.f;

    auto load_stage = [&](int s) {
        const int k0 = s * 64;
        const uint32_t stg = sb + (uint32_t)(s % 3) * QK_STG;
        #pragma unroll
        for (int i = 0; i < 8; i++) {
            int idx = tid + (i << 9);           // 0..4095
            if (idx < 2048) {
                int mat = idx >> 10;
                int row = (idx >> 3) & 127;
                int q   = idx & 7;
                const __nv_bfloat16* src =
                    (mat ? Al : Ah) + (size_t)(m0 + row) * K + k0 + q * 8;
                cp16(stg + mat * 16384 + sw128((uint32_t)(row * 128 + q * 16)), src);
            } else {
                int rel = idx - 2048;
                int mat = rel >> 10;
                int row = (rel >> 3) & 127;
                int q   = rel & 7;
                const __nv_bfloat16* src =
                    (mat ? BTl : BTh) + (size_t)(n0 + row) * K + k0 + q * 8;
                cp16(stg + 32768 + mat * 16384 + sw128((uint32_t)(row * 128 + q * 16)), src);
            }
        }
    };

    load_stage(0);
    asm volatile("cp.async.commit_group;" ::: "memory");
    load_stage(1);
    asm volatile("cp.async.commit_group;" ::: "memory");

    const int aRow  = (lane & 15);
    const int aKoff = (lane >> 4) << 4;
    const int bRow  = (lane & 7) + ((lane >> 4) << 3);
    const int bKoff = ((lane >> 3) & 1) << 4;

    for (int s = 0; s < nstage; s++) {
        if (s + 1 < nstage) asm volatile("cp.async.wait_group 1;" ::: "memory");
        else                asm volatile("cp.async.wait_group 0;" ::: "memory");
        __syncthreads();
        if (s + 2 < nstage) {
            load_stage(s + 2);
            asm volatile("cp.async.commit_group;" ::: "memory");
        }

        const uint32_t ab = sb + (uint32_t)(s % 3) * QK_STG;

        #pragma unroll
        for (int kk = 0; kk < 4; kk++) {
            const int kb = kk * 32;
            uint32_t b_h[8], b_l[8];
            #pragma unroll
            for (int ib = 0; ib < 2; ib++) {
                uint32_t off = sw128((uint32_t)((wn * 32 + ib * 16 + bRow) * 128 + kb + bKoff));
                ldsm4(&b_h[ib * 4], ab + 32768 + off);
                ldsm4(&b_l[ib * 4], ab + 49152 + off);
            }
            #pragma unroll
            for (int im = 0; im < 2; im++) {
                uint32_t a_h[4], a_l[4];
                uint32_t off = sw128((uint32_t)((wm * 32 + im * 16 + aRow) * 128 + kb + aKoff));
                ldsm4(a_h, ab + off);
                ldsm4(a_l, ab + 16384 + off);
                #pragma unroll
                for (int in = 0; in < 4; in++) {
                    const uint32_t* bh = &b_h[(in >> 1) * 4 + (in & 1) * 2];
                    const uint32_t* bl = &b_l[(in >> 1) * 4 + (in & 1) * 2];
                    mma16816(c[im][in], a_h, bh);
                    mma16816(c[im][in], a_l, bh);
                    mma16816(c[im][in], a_h, bl);
                }
            }
        }
    }
}

// fp16 core for V tiles (512 threads, warp tile 32x32), ring-3 32KB stages
#define VH_STG 32768
__device__ __forceinline__ void gemm_core_h512(
    const __half* __restrict__ A, const __half* __restrict__ BT,
    int K, int m0, int n0, uint32_t sb, int tid, float c[2][4][4])
{
    const int lane = tid & 31;
    const int wm   = (tid >> 5) >> 2;
    const int wn   = (tid >> 5) & 3;
    const int nstage = K / 64;

    #pragma unroll
    for (int im = 0; im < 2; im++)
        #pragma unroll
        for (int in = 0; in < 4; in++)
            #pragma unroll
            for (int j = 0; j < 4; j++) c[im][in][j] = 0.f;

    auto load_stage = [&](int s) {
        const int k0 = s * 64;
        const uint32_t stg = sb + (uint32_t)(s % 3) * VH_STG;
        #pragma unroll
        for (int i = 0; i < 4; i++) {
            int idx = tid + (i << 9);           // 0..2047
            if (idx < 1024) {
                int row = idx >> 3, q = idx & 7;
                cp16(stg + sw128((uint32_t)(row * 128 + q * 16)),
                     A + (size_t)(m0 + row) * K + k0 + q * 8);
            } else {
                int rel = idx - 1024;
                int row = rel >> 3, q = rel & 7;
                cp16(stg + 16384 + sw128((uint32_t)(row * 128 + q * 16)),
                     BT + (size_t)(n0 + row) * K + k0 + q * 8);
            }
        }
    };

    load_stage(0);
    asm volatile("cp.async.commit_group;" ::: "memory");
    load_stage(1);
    asm volatile("cp.async.commit_group;" ::: "memory");

    const int aRow  = (lane & 15);
    const int aKoff = (lane >> 4) << 4;
    const int bRow  = (lane & 7) + ((lane >> 4) << 3);
    const int bKoff = ((lane >> 3) & 1) << 4;

    for (int s = 0; s < nstage; s++) {
        if (s + 1 < nstage) asm volatile("cp.async.wait_group 1;" ::: "memory");
        else                asm volatile("cp.async.wait_group 0;" ::: "memory");
        __syncthreads();
        if (s + 2 < nstage) {
            load_stage(s + 2);
            asm volatile("cp.async.commit_group;" ::: "memory");
        }

        const uint32_t ab = sb + (uint32_t)(s % 3) * VH_STG;

        #pragma unroll
        for (int kk = 0; kk < 4; kk++) {
            const int kb = kk * 32;
            uint32_t b_f[8];
            #pragma unroll
            for (int ib = 0; ib < 2; ib++) {
                uint32_t off = sw128((uint32_t)((wn * 32 + ib * 16 + bRow) * 128 + kb + bKoff));
                ldsm4(&b_f[ib * 4], ab + 16384 + off);
            }
            #pragma unroll
            for (int im = 0; im < 2; im++) {
                uint32_t a_f[4];
                uint32_t off = sw128((uint32_t)((wm * 32 + im * 16 + aRow) * 128 + kb + aKoff));
                ldsm4(a_f, ab + off);
                #pragma unroll
                for (int in = 0; in < 4; in++)
                    mma16816h(c[im][in], a_f, &b_f[(in >> 1) * 4 + (in & 1) * 2]);
            }
        }
    }
}

// ---------------------------------------------------------------------------
// QKV GEMM, persistent work-stealing over 768 BM128xBN128 tiles:
// tiles [0,640) = QK split-bf16 (+RoPE), [640,768) = V fp16. 148 CTAs, 512 thr.
// ---------------------------------------------------------------------------
__global__ void __launch_bounds__(512, 1)
gemm_qkv_kernel(const __nv_bfloat16* __restrict__ Ah, const __nv_bfloat16* __restrict__ Al,
                const __nv_bfloat16* __restrict__ BTh, const __nv_bfloat16* __restrict__ BTl,
                const __half* __restrict__ x16, const __half* __restrict__ wv16,
                const float* __restrict__ bq, const float* __restrict__ bk,
                const float* __restrict__ bv,
                const float* __restrict__ ct, const float* __restrict__ st,
                __nv_bfloat16* __restrict__ qr, __nv_bfloat16* __restrict__ kr,
                __half* __restrict__ v16, uint32_t* __restrict__ ctr)
{
    extern __shared__ char dsm[];
    char* smbase = (char*)(((uintptr_t)dsm + 1023) & ~(uintptr_t)1023);
    const uint32_t sb = smem_u32(smbase);
    const int tid  = threadIdx.x;
    const int lane = tid & 31;
    const int wm   = (tid >> 5) >> 2;
    const int wn   = (tid >> 5) & 3;

    __shared__ int s_tile;

    for (;;) {
        if (tid == 0) s_tile = (int)atomicAdd(ctr, 1u);
        __syncthreads();               // also orders previous tile's compute
        const int lin = s_tile;
        if (lin >= 768) return;

        int colt, rowt, region;
        if (lin < 640) {
            colt = lin % 20; rowt = lin / 20;
            region = (colt >= 16) ? 1 : 0;
        } else {
            int v = lin - 640;
            colt = 20 + (v & 3); rowt = v >> 2; region = 2;
        }
        const int m0 = rowt * 128;
        const int n0 = colt * 128;

        float c[2][4][4];
        if (region == 2) {
            gemm_core_h512(x16, wv16, NE, m0, n0 - NQK, sb, tid, c);
        } else {
            gemm_core(Ah, Al, BTh, BTl, NE, m0, n0, sb, tid, c);
        }

        #pragma unroll
        for (int im = 0; im < 2; im++) {
            const int r0 = m0 + wm * 32 + im * 16 + (lane >> 2);
            const int b  = r0 >> 11;
            const int t  = r0 & 2047;
            #pragma unroll
            for (int in = 0; in < 4; in++) {
                const int cc = n0 + wn * 32 + in * 8 + ((lane & 3) << 1);
                float b0, b1;
                if (region == 0)      { b0 = bq[cc];       b1 = bq[cc + 1]; }
                else if (region == 1) { b0 = bk[cc - NE];  b1 = bk[cc - NE + 1]; }
                else                  { b0 = bv[cc - NQK]; b1 = bv[cc - NQK + 1]; }
                float v0 = c[im][in][0] + b0, v1 = c[im][in][1] + b1;   // row t
                float v2 = c[im][in][2] + b0, v3 = c[im][in][3] + b1;   // row t+8
                const int dloc = cc & 127;
                if (region <= 1) {
                    const int i  = dloc >> 1;
                    float c0 = ct[t * 64 + i],       s0 = st[t * 64 + i];
                    float c2 = ct[(t + 8) * 64 + i], s2 = st[(t + 8) * 64 + i];
                    uint32_t p0 = cvtpack(v0 * c0 - v1 * s0, v0 * s0 + v1 * c0);
                    uint32_t p2 = cvtpack(v2 * c2 - v3 * s2, v2 * s2 + v3 * c2);
                    if (region == 0) {
                        const int h = cc >> 7;
                        size_t dst = ((size_t)((b * NH + h) * TT + t)) * HD + dloc;
                        *(uint32_t*)(qr + dst)          = p0;
                        *(uint32_t*)(qr + dst + 8 * HD) = p2;
                    } else {
                        const int h = (cc - NE) >> 7;
                        size_t dst = ((size_t)((b * NKV + h) * TT + t)) * HD + dloc;
                        *(uint32_t*)(kr + dst)          = p0;
                        *(uint32_t*)(kr + dst + 8 * HD) = p2;
                    }
                } else {
                    const int h = (cc - NQK) >> 7;
                    size_t dst = ((size_t)((b * NKV + h) * TT + t)) * HD + dloc;
                    *(uint32_t*)(v16 + dst)          = cvtpackh(v0, v1);
                    *(uint32_t*)(v16 + dst + 8 * HD) = cvtpackh(v2, v3);
                }
            }
        }
    }
}

// ---------------------------------------------------------------------------
// O-proj core: fp16 single-term, 256 threads (2m x 4n warps, warp tile 64x32),
// BM=128, BN=128, ring-3 32KB stages -> 2 CTAs/SM.
// ---------------------------------------------------------------------------
#define OSTG 32768
#define GEMMO_SMEM (3*OSTG + 1024)

__global__ void __launch_bounds__(256, 2)
gemm_out_kernel(const __half* __restrict__ A, const __half* __restrict__ BT,
                const float* __restrict__ bias, float* __restrict__ C,
                uint32_t* __restrict__ ctr)
{
    extern __shared__ char dsm[];
    char* smbase = (char*)(((uintptr_t)dsm + 1023) & ~(uintptr_t)1023);
    const uint32_t sb = smem_u32(smbase);
    const int tid  = threadIdx.x;
    const int lane = tid & 31;
    const int wm   = (tid >> 5) >> 2;   // 0..1 (64 rows each)
    const int wn   = (tid >> 5) & 3;    // 0..3 (32 cols each)
    const int nstage = NE / 64;

    __shared__ int s_tile;

    const int aRow  = (lane & 15);
    const int aKoff = (lane >> 4) << 4;
    const int bRow  = (lane & 7) + ((lane >> 4) << 3);
    const int bKoff = ((lane >> 3) & 1) << 4;

    for (;;) {
        if (tid == 0) s_tile = (int)atomicAdd(ctr, 1u);
        __syncthreads();
        const int lin = s_tile;
        if (lin >= 512) return;
        const int m0 = (lin >> 4) * 128;
        const int n0 = (lin & 15) * 128;

        float c[4][4][4];
        #pragma unroll
        for (int im = 0; im < 4; im++)
            #pragma unroll
            for (int in = 0; in < 4; in++)
                #pragma unroll
                for (int j = 0; j < 4; j++) c[im][in][j] = 0.f;

        auto load_stage = [&](int s) {
            const int k0 = s * 64;
            const uint32_t stg = sb + (uint32_t)(s % 3) * OSTG;
            #pragma unroll
            for (int i = 0; i < 8; i++) {
                int idx = tid + (i << 8);       // 0..2047
                if (idx < 1024) {
                    int row = idx >> 3, q = idx & 7;
                    cp16(stg + sw128((uint32_t)(row * 128 + q * 16)),
                         A + (size_t)(m0 + row) * NE + k0 + q * 8);
                } else {
                    int rel = idx - 1024;
                    int row = rel >> 3, q = rel & 7;
                    cp16(stg + 16384 + sw128((uint32_t)(row * 128 + q * 16)),
                         BT + (size_t)(n0 + row) * NE + k0 + q * 8);
                }
            }
        };

        load_stage(0);
        asm volatile("cp.async.commit_group;" ::: "memory");
        load_stage(1);
        asm volatile("cp.async.commit_group;" ::: "memory");

        for (int s = 0; s < nstage; s++) {
            if (s + 1 < nstage) asm volatile("cp.async.wait_group 1;" ::: "memory");
            else                asm volatile("cp.async.wait_group 0;" ::: "memory");
            __syncthreads();
            if (s + 2 < nstage) {
                load_stage(s + 2);
                asm volatile("cp.async.commit_group;" ::: "memory");
            }

            const uint32_t ab = sb + (uint32_t)(s % 3) * OSTG;

            #pragma unroll
            for (int kk = 0; kk < 4; kk++) {
                const int kb = kk * 32;
                uint32_t b_f[8];
                #pragma unroll
                for (int ib = 0; ib < 2; ib++) {
                    uint32_t off = sw128((uint32_t)((wn * 32 + ib * 16 + bRow) * 128 + kb + bKoff));
                    ldsm4(&b_f[ib * 4], ab + 16384 + off);
                }
                #pragma unroll
                for (int im = 0; im < 4; im++) {
                    uint32_t a_f[4];
                    uint32_t off = sw128((uint32_t)((wm * 64 + im * 16 + aRow) * 128 + kb + aKoff));
                    ldsm4(a_f, ab + off);
                    #pragma unroll
                    for (int in = 0; in < 4; in++)
                        mma16816h(c[im][in], a_f, &b_f[(in >> 1) * 4 + (in & 1) * 2]);
                }
            }
        }

        #pragma unroll
        for (int im = 0; im < 4; im++) {
            const int r0 = m0 + wm * 64 + im * 16 + (lane >> 2);
            #pragma unroll
            for (int in = 0; in < 4; in++) {
                const int cc = n0 + wn * 32 + in * 8 + ((lane & 3) << 1);
                float2 bb = *(const float2*)&bias[cc];
                float2 o0, o1;
                o0.x = c[im][in][0] + bb.x;  o0.y = c[im][in][1] + bb.y;
                o1.x = c[im][in][2] + bb.x;  o1.y = c[im][in][3] + bb.y;
                *(float2*)&C[(size_t)r0 * NE + cc]       = o0;
                *(float2*)&C[(size_t)(r0 + 8) * NE + cc] = o1;
            }
        }
    }
}

// ---------------------------------------------------------------------------
// Flash attention (unchanged from R16). BM=64, BN=64, 128 threads, 3 CTAs/SM.
// ---------------------------------------------------------------------------
#define AT_RS 272
#define AT_T64 (64 * AT_RS)
#define ATT_SMEM (4 * AT_T64 + 1024)

__global__ void __launch_bounds__(128, 3)
attn_mma_kernel(const __nv_bfloat16* __restrict__ qr, const __nv_bfloat16* __restrict__ kr,
                const __half* __restrict__ v16, __half* __restrict__ o16)
{
    extern __shared__ char dsm2[];
    char* smb = (char*)(((uintptr_t)dsm2 + 1023) & ~(uintptr_t)1023);
    const uint32_t sb = smem_u32(smb);

    const int tid  = threadIdx.x;
    const int lane = tid & 31;
    const int w    = tid >> 5;
    const int mtb  = (int)gridDim.x - 1 - (int)blockIdx.x;
    const int h    = blockIdx.y, b = blockIdx.z;
    const int m0   = mtb * 64;
    const int kv   = h >> 2;
    const int ntile = mtb + 1;

    const __nv_bfloat16* qg = qr  + ((size_t)(b * NH + h) * TT + m0) * HD;
    const __nv_bfloat16* kg = kr  + ((size_t)(b * NKV + kv) * TT) * HD;
    const __half*        vg = v16 + ((size_t)(b * NKV + kv) * TT) * HD;

    auto toff = [&](int buf, int which) -> uint32_t {
        return sb + (uint32_t)AT_T64 * (buf * 2 + which);
    };
    const uint32_t Q0 = toff(1, 0);
    auto load64 = [&](uint32_t dst, const void* srcbase, int tile) {
        const char* src = (const char*)srcbase + (size_t)tile * 64 * HD * 2;
        #pragma unroll
        for (int i = 0; i < 8; i++) {
            int idx = tid + i * 128;
            int row = idx >> 4, cq = idx & 15;
            cp16(dst + (uint32_t)(row * AT_RS + cq * 16), src + (size_t)row * HD * 2 + cq * 16);
        }
    };

    load64(Q0, qg, 0);
    load64(toff(0, 0), kg, 0);
    load64(toff(0, 1), vg, 0);
    asm volatile("cp.async.commit_group;" ::: "memory");

    uint32_t qf[8][4];
    float ov[16][4];
    #pragma unroll
    for (int n = 0; n < 16; n++) { ov[n][0] = ov[n][1] = ov[n][2] = ov[n][3] = 0.f; }
    float m_lo = -1e30f, m_hi = -1e30f, l_lo = 0.f, l_hi = 0.f;

    const int aRow = lane & 15;
    const int aK   = (lane >> 4) << 4;
    const int bRow = (lane & 7) + ((lane >> 4) << 3);
    const int bK   = ((lane >> 3) & 1) << 4;
    const int vRow = (lane & 7) + (((lane >> 3) & 1) << 3);
    const int vC   = (lane >> 4) << 4;

    for (int jt = 0; jt < ntile; jt++) {
        asm volatile("cp.async.wait_group 0;" ::: "memory");
        __syncthreads();
        if (jt == 0) {
            #pragma unroll
            for (int kt = 0; kt < 8; kt++)
                ldsm4(qf[kt], Q0 + (uint32_t)((w * 16 + aRow) * AT_RS + kt * 32 + aK));
            __syncthreads();
        }
        if (jt + 1 < ntile) {
            int nb = (jt + 1) & 1;
            load64(toff(nb, 0), kg, jt + 1);
            load64(toff(nb, 1), vg, jt + 1);
            asm volatile("cp.async.commit_group;" ::: "memory");
        }

        const int cbuf = jt & 1;
        const uint32_t kb = toff(cbuf, 0);
        const uint32_t vb = toff(cbuf, 1);

        float sc[8][4];
        #pragma unroll
        for (int j = 0; j < 8; j++) { sc[j][0] = sc[j][1] = sc[j][2] = sc[j][3] = 0.f; }

        #pragma unroll
        for (int kt = 0; kt < 8; kt++) {
            #pragma unroll
            for (int ib = 0; ib < 4; ib++) {
                uint32_t bf[4];
                ldsm4(bf, kb + (uint32_t)((ib * 16 + bRow) * AT_RS + kt * 32 + bK));
                mma16816(sc[2 * ib],     qf[kt], bf);
                mma16816(sc[2 * ib + 1], qf[kt], bf + 2);
            }
        }

        if (jt == ntile - 1) {
            const int rl = w * 16 + (lane >> 2);
            #pragma unroll
            for (int j = 0; j < 8; j++) {
                int gn = j * 8 + ((lane & 3) << 1);
                if (gn     > rl)     sc[j][0] = -1e30f;
                if (gn + 1 > rl)     sc[j][1] = -1e30f;
                if (gn     > rl + 8) sc[j][2] = -1e30f;
                if (gn + 1 > rl + 8) sc[j][3] = -1e30f;
            }
        }

        float vlo = -1e30f, vhi = -1e30f;
        #pragma unroll
        for (int j = 0; j < 8; j++) {
            vlo = fmaxf(vlo, fmaxf(sc[j][0], sc[j][1]));
            vhi = fmaxf(vhi, fmaxf(sc[j][2], sc[j][3]));
        }
        vlo = fmaxf(vlo, __shfl_xor_sync(0xffffffffu, vlo, 1));
        vlo = fmaxf(vlo, __shfl_xor_sync(0xffffffffu, vlo, 2));
        vhi = fmaxf(vhi, __shfl_xor_sync(0xffffffffu, vhi, 1));
        vhi = fmaxf(vhi, __shfl_xor_sync(0xffffffffu, vhi, 2));
        float mn_lo = fmaxf(m_lo, vlo), mn_hi = fmaxf(m_hi, vhi);
        float al_lo = __expf(m_lo - mn_lo), al_hi = __expf(m_hi - mn_hi);
        m_lo = mn_lo; m_hi = mn_hi;
        l_lo *= al_lo; l_hi *= al_hi;
        #pragma unroll
        for (int n = 0; n < 16; n++) {
            ov[n][0] *= al_lo; ov[n][1] *= al_lo;
            ov[n][2] *= al_hi; ov[n][3] *= al_hi;
        }

        uint32_t ph[8][2];
        #pragma unroll
        for (int j = 0; j < 8; j++) {
            float p0 = __expf(sc[j][0] - m_lo), p1 = __expf(sc[j][1] - m_lo);
            float p2 = __expf(sc[j][2] - m_hi), p3 = __expf(sc[j][3] - m_hi);
            l_lo += p0 + p1;  l_hi += p2 + p3;
            ph[j][0] = cvtpackh(p0, p1);
            ph[j][1] = cvtpackh(p2, p3);
        }

        #pragma unroll
        for (int kt = 0; kt < 4; kt++) {
            uint32_t ah[4] = { ph[2*kt][0], ph[2*kt][1], ph[2*kt+1][0], ph[2*kt+1][1] };
            #pragma unroll
            for (int np = 0; np < 4; np++) {
                uint32_t base = (uint32_t)((kt * 16 + vRow) * AT_RS + np * 64 + vC);
                uint32_t bh0[4], bh1[4];
                ldsm4t(bh0, vb + base);
                ldsm4t(bh1, vb + base + 32);
                mma16816h(ov[np*4+0], ah, bh0);
                mma16816h(ov[np*4+1], ah, bh0 + 2);
                mma16816h(ov[np*4+2], ah, bh1);
                mma16816h(ov[np*4+3], ah, bh1 + 2);
            }
        }
    }

    l_lo += __shfl_xor_sync(0xffffffffu, l_lo, 1);
    l_lo += __shfl_xor_sync(0xffffffffu, l_lo, 2);
    l_hi += __shfl_xor_sync(0xffffffffu, l_hi, 1);
    l_hi += __shfl_xor_sync(0xffffffffu, l_hi, 2);
    const float inv_lo = 0.022097086912079608f / l_lo;
    const float inv_hi = 0.022097086912079608f / l_hi;
    const int rlo = m0 + w * 16 + (lane >> 2);
    size_t base = ((size_t)(b * TT) + rlo) * NE + h * HD;
    #pragma unroll
    for (int n = 0; n < 16; n++) {
        int d = n * 8 + ((lane & 3) << 1);
        *(uint32_t*)(o16 + base + d)          = cvtpackh(ov[n][0] * inv_lo, ov[n][1] * inv_lo);
        *(uint32_t*)(o16 + base + 8 * NE + d) = cvtpackh(ov[n][2] * inv_hi, ov[n][3] * inv_hi);
    }
}

// ---------------------------------------------------------------------------
// launch
// ---------------------------------------------------------------------------
extern "C" void kernel_launch(void* const* d_in, const int* in_sizes, int n_in,
                              void* d_out, int out_size)
{
    const float* x  = (const float*)d_in[0];
    const float* Wq = (const float*)d_in[1];
    const float* bq = (const float*)d_in[2];
    const float* Wk = (const float*)d_in[3];
    const float* bk = (const float*)d_in[4];
    const float* Wv = (const float*)d_in[5];
    const float* bv = (const float*)d_in[6];
    const float* Wo = (const float*)d_in[7];
    const float* bo = (const float*)d_in[8];
    float* out = (float*)d_out;

    float *ct, *st;
    __nv_bfloat16 *qr, *kr;
    __half *v16, *o16, *x16, *wv16, *wo16;
    __nv_bfloat16 *xh, *xl;
    __nv_bfloat16 *wqkh, *wqkl;
    uint32_t* ctr;
    cudaGetSymbolAddress((void**)&ct, g_cos);
    cudaGetSymbolAddress((void**)&st, g_sin);
    cudaGetSymbolAddress((void**)&qr, g_qr);
    cudaGetSymbolAddress((void**)&kr, g_kr);
    cudaGetSymbolAddress((void**)&v16, g_v16);
    cudaGetSymbolAddress((void**)&o16, g_o16);
    cudaGetSymbolAddress((void**)&x16, g_x16);
    cudaGetSymbolAddress((void**)&xh, g_xh);
    cudaGetSymbolAddress((void**)&xl, g_xl);
    cudaGetSymbolAddress((void**)&wqkh, g_wqkh);
    cudaGetSymbolAddress((void**)&wqkl, g_wqkl);
    cudaGetSymbolAddress((void**)&wv16, g_wv16);
    cudaGetSymbolAddress((void**)&wo16, g_wo16);
    cudaGetSymbolAddress((void**)&ctr, g_ctr);

    cudaFuncSetAttribute(gemm_qkv_kernel, cudaFuncAttributeMaxDynamicSharedMemorySize, GEMM_SMEM);
    cudaFuncSetAttribute(gemm_out_kernel, cudaFuncAttributeMaxDynamicSharedMemorySize, GEMMO_SMEM);
    cudaFuncSetAttribute(attn_mma_kernel, cudaFuncAttributeMaxDynamicSharedMemorySize, ATT_SMEM);

    // zero work-steal counters (graph-capturable)
    cudaMemsetAsync(ctr, 0, 2 * sizeof(uint32_t));

    // fused prep (1 launch)
    prep_kernel<<<14848, 256>>>(Wq, Wk, Wv, Wo, x, wqkh, wqkl, wv16, wo16,
                                xh, xl, x16, ct, st);

    // fused QKV projection: persistent 148 CTAs, 768 BM128 tiles (QK first)
    gemm_qkv_kernel<<<NSM, 512, GEMM_SMEM>>>(
        xh, xl, wqkh, wqkl, x16, wv16, bq, bk, bv, ct, st, qr, kr, v16, ctr);

    // attention (writes fp16 o16); 3 CTAs/SM
    {
        dim3 grid(TT / 64, NH, BB);
        attn_mma_kernel<<<grid, 128, ATT_SMEM>>>(qr, kr, v16, o16);
    }

    // output projection: fp16 single-term, persistent 296 CTAs (2/SM)
    gemm_out_kernel<<<2 * NSM, 256, GEMMO_SMEM>>>(o16, wo16, bo, out, ctr + 1);
}